// round 1
// baseline (speedup 1.0000x reference)
#include <cuda_runtime.h>
#include <math.h>

#define Bb 4
#define Tt 1024
#define Ee 512
#define Ss 1536
#define Hh 1024
#define NHh 16
#define HDd 64

// ---- scratch (static device globals; no allocation allowed) ----
__device__ float g_qp[(size_t)Bb*Tt*Hh];                 // q projection (pre-scaled)
__device__ float g_kp[(size_t)Bb*Tt*Hh];                 // k projection
__device__ float g_vp[(size_t)Bb*Tt*Hh];                 // v projection
__device__ float g_qr[(size_t)Bb*NHh*Tt*HDd];            // q roped   [B,NH,T,D]
__device__ float g_kr[(size_t)Bb*NHh*Ss*HDd];            // k expanded+roped [B,NH,S,D]
__device__ float g_vr[(size_t)Bb*NHh*Ss*HDd];            // v expanded       [B,NH,S,D]
__device__ float g_attn[(size_t)Bb*Tt*Hh];               // attention out [B,T,H]
__device__ float g_norm[(size_t)Bb*Tt*Hh];               // layernorm out

// ---- C[m,n] = alpha * sum_k X[m,k] * W[n,k]   (torch Linear: x @ W^T) ----
__global__ void gemm_xwt(const float* __restrict__ X, const float* __restrict__ W,
                         float* __restrict__ C, int M, int N, int K, float alpha)
{
    const int BM = 64, BN = 64, BK = 16;
    __shared__ float As[BK][BM];
    __shared__ float Bs[BK][BN];
    int m0 = blockIdx.y * BM;
    int n0 = blockIdx.x * BN;
    int tx = threadIdx.x, ty = threadIdx.y;       // 16 x 16
    int tid = ty * 16 + tx;
    float acc[4][4] = {};
    for (int k0 = 0; k0 < K; k0 += BK) {
        #pragma unroll
        for (int i = tid; i < BM * BK; i += 256) {
            int r = i / BK, kk = i % BK;
            As[kk][r] = X[(size_t)(m0 + r) * K + k0 + kk];
        }
        #pragma unroll
        for (int i = tid; i < BN * BK; i += 256) {
            int c = i / BK, kk = i % BK;
            Bs[kk][c] = W[(size_t)(n0 + c) * K + k0 + kk];
        }
        __syncthreads();
        #pragma unroll
        for (int kk = 0; kk < BK; kk++) {
            float ra[4], rb[4];
            #pragma unroll
            for (int a = 0; a < 4; a++) ra[a] = As[kk][ty * 4 + a];
            #pragma unroll
            for (int b2 = 0; b2 < 4; b2++) rb[b2] = Bs[kk][tx * 4 + b2];
            #pragma unroll
            for (int a = 0; a < 4; a++)
                #pragma unroll
                for (int b2 = 0; b2 < 4; b2++)
                    acc[a][b2] += ra[a] * rb[b2];
        }
        __syncthreads();
    }
    #pragma unroll
    for (int a = 0; a < 4; a++)
        #pragma unroll
        for (int b2 = 0; b2 < 4; b2++)
            C[(size_t)(m0 + ty * 4 + a) * N + n0 + tx * 4 + b2] = alpha * acc[a][b2];
}

// ---- PBC expand + RoPE: grid (S, NH, B), 64 threads ----
__global__ void rope_expand(const int* __restrict__ outcell)
{
    int s = blockIdx.x, h = blockIdx.y, b = blockIdx.z;
    int tid = threadIdx.x;   // 64
    int src = (s < Tt) ? s : outcell[b * Ee + (s - Tt)];
    const float* kp = g_kp + ((size_t)b * Tt + src) * Hh + h * HDd;
    const float* vp = g_vp + ((size_t)b * Tt + src) * Hh + h * HDd;
    float* krow = g_kr + (((size_t)b * NHh + h) * Ss + s) * HDd;
    float* vrow = g_vr + (((size_t)b * NHh + h) * Ss + s) * HDd;
    vrow[tid] = vp[tid];
    if (tid < 32) {
        // inv_freq[j] = 10000^(-2j/64); position = concatenated index s
        float invf = expf(-((float)(2 * tid) / 64.0f) * logf(10000.0f));
        float ang = (float)s * invf;
        float c = cosf(ang), sn = sinf(ang);
        float x1 = kp[tid], x2 = kp[tid + 32];
        krow[tid]      = x1 * c - x2 * sn;
        krow[tid + 32] = x2 * c + x1 * sn;
        if (s < Tt) {
            const float* qp = g_qp + ((size_t)b * Tt + s) * Hh + h * HDd;
            float* qrow = g_qr + (((size_t)b * NHh + h) * Tt + s) * HDd;
            float y1 = qp[tid], y2 = qp[tid + 32];
            qrow[tid]      = y1 * c - y2 * sn;
            qrow[tid + 32] = y2 * c + y1 * sn;
        }
    }
}

// ---- attention: one block per (q, h, b); 128 threads ----
__global__ void attn_kernel(const float* __restrict__ bias,
                            const float* __restrict__ lw,
                            const unsigned char* __restrict__ kpm,
                            const unsigned char* __restrict__ em)
{
    int q = blockIdx.x, h = blockIdx.y, b = blockIdx.z;
    int tid = threadIdx.x;   // 128
    __shared__ float qs[HDd];
    __shared__ float sc[Ss];
    __shared__ float red[128];

    const float* qrow = g_qr + (((size_t)b * NHh + h) * Tt + q) * HDd;
    if (tid < HDd) qs[tid] = qrow[tid];
    __syncthreads();

    const float* Kb    = g_kr + ((size_t)b * NHh + h) * (size_t)Ss * HDd;
    const float* brow  = bias + (((size_t)b * NHh + h) * Tt + q) * (size_t)Ss;
    const float* lwrow = lw + ((size_t)b * Tt + q) * (size_t)Ss;

    // pass 1: scores + masks + running max
    float lmax = -INFINITY;
    for (int k = tid; k < Ss; k += 128) {
        const float4* kp4 = (const float4*)(Kb + (size_t)k * HDd);
        const float4* q4 = (const float4*)qs;
        float dot = 0.f;
        #pragma unroll
        for (int i = 0; i < 16; i++) {
            float4 kv = kp4[i]; float4 qv = q4[i];
            dot += kv.x * qv.x; dot += kv.y * qv.y;
            dot += kv.z * qv.z; dot += kv.w * qv.w;
        }
        float sval = dot + brow[k];
        bool masked = (lwrow[k] <= 1e-5f);
        if (k < Tt) masked = masked || (kpm[b * Tt + k] != 0);
        else        masked = masked || (em[b * Ee + (k - Tt)] != 0);
        sval = masked ? -INFINITY : sval;
        sc[k] = sval;
        lmax = fmaxf(lmax, sval);
    }
    red[tid] = lmax;
    __syncthreads();
    for (int st = 64; st > 0; st >>= 1) {
        if (tid < st) red[tid] = fmaxf(red[tid], red[tid + st]);
        __syncthreads();
    }
    float m = red[0];
    __syncthreads();

    // pass 2: exp, denominator over raw exp; store exp * local_weight
    float lsum = 0.f;
    for (int k = tid; k < Ss; k += 128) {
        float e = expf(sc[k] - m);     // -inf -> 0
        sc[k] = e * lwrow[k];
        lsum += e;
    }
    red[tid] = lsum;
    __syncthreads();
    for (int st = 64; st > 0; st >>= 1) {
        if (tid < st) red[tid] += red[tid + st];
        __syncthreads();
    }
    float inv = 1.0f / red[0];
    __syncthreads();

    // pass 3: PV.  thread = (half of keys, output dim)
    const float* Vb = g_vr + ((size_t)b * NHh + h) * (size_t)Ss * HDd;
    int half = tid >> 6, d = tid & 63;
    float acc = 0.f;
    int kbeg = half * (Ss / 2), kend = kbeg + (Ss / 2);
    for (int k = kbeg; k < kend; k++)
        acc += sc[k] * Vb[(size_t)k * HDd + d];
    red[tid] = acc;
    __syncthreads();
    if (tid < HDd)
        g_attn[((size_t)b * Tt + q) * Hh + h * HDd + tid] =
            (red[tid] + red[tid + 64]) * inv;
}

// ---- layernorm over H=1024: one block per row, 256 threads ----
__global__ void ln_kernel(const float* __restrict__ gamma, const float* __restrict__ beta)
{
    int row = blockIdx.x;
    int tid = threadIdx.x;   // 256
    const float* in = g_attn + (size_t)row * Hh;
    float* out = g_norm + (size_t)row * Hh;
    float s = 0.f, s2 = 0.f;
    float vals[4];
    #pragma unroll
    for (int i = 0; i < 4; i++) {
        float v = in[tid + i * 256];
        vals[i] = v; s += v; s2 += v * v;
    }
    __shared__ float rs[256], rs2[256];
    rs[tid] = s; rs2[tid] = s2;
    __syncthreads();
    for (int st = 128; st > 0; st >>= 1) {
        if (tid < st) { rs[tid] += rs[tid + st]; rs2[tid] += rs2[tid + st]; }
        __syncthreads();
    }
    float mean = rs[0] * (1.0f / Hh);
    float var  = rs2[0] * (1.0f / Hh) - mean * mean;
    float r = rsqrtf(var + 1e-5f);
    #pragma unroll
    for (int i = 0; i < 4; i++) {
        int c = tid + i * 256;
        out[c] = (vals[i] - mean) * r * gamma[c] + beta[c];
    }
}

extern "C" void kernel_launch(void* const* d_in, const int* in_sizes, int n_in,
                              void* d_out, int out_size)
{
    const float* x    = (const float*)d_in[0];
    const float* bias = (const float*)d_in[1];
    const float* lw   = (const float*)d_in[2];
    const unsigned char* kpm = (const unsigned char*)d_in[3];
    const int*   outcell = (const int*)d_in[4];
    const unsigned char* em  = (const unsigned char*)d_in[5];
    const float* wq   = (const float*)d_in[6];
    const float* wk   = (const float*)d_in[7];
    const float* wv   = (const float*)d_in[8];
    const float* wout = (const float*)d_in[9];
    const float* lng  = (const float*)d_in[10];
    const float* lnb  = (const float*)d_in[11];

    float *qp, *kp, *vp, *nrm;
    cudaGetSymbolAddress((void**)&qp,  g_qp);
    cudaGetSymbolAddress((void**)&kp,  g_kp);
    cudaGetSymbolAddress((void**)&vp,  g_vp);
    cudaGetSymbolAddress((void**)&nrm, g_norm);

    dim3 gt(16, 16);
    dim3 gg(Hh / 64, (Bb * Tt) / 64);
    // SCALING = sqrt(64)/64 = 0.125, folded into the q projection
    gemm_xwt<<<gg, gt>>>(x, wq, qp, Bb * Tt, Hh, Hh, 0.125f);
    gemm_xwt<<<gg, gt>>>(x, wk, kp, Bb * Tt, Hh, Hh, 1.0f);
    gemm_xwt<<<gg, gt>>>(x, wv, vp, Bb * Tt, Hh, Hh, 1.0f);
    rope_expand<<<dim3(Ss, NHh, Bb), 64>>>(outcell);
    attn_kernel<<<dim3(Tt, NHh, Bb), 128>>>(bias, lw, kpm, em);
    ln_kernel<<<Bb * Tt, 256>>>(lng, lnb);
    gemm_xwt<<<gg, gt>>>(nrm, wout, (float*)d_out, Bb * Tt, Hh, Hh, 1.0f);
}

// round 2
// speedup vs baseline: 3.0178x; 3.0178x over previous
#include <cuda_runtime.h>
#include <math.h>

#define Bb 4
#define Tt 1024
#define Ee 512
#define Ss 1536
#define Hh 1024
#define NHh 16
#define HDd 64
#define QT 16

// ---- scratch (static device globals; no allocation allowed) ----
__device__ float g_qp[(size_t)Bb*Tt*Hh];
__device__ float g_kp[(size_t)Bb*Tt*Hh];
__device__ float g_vp[(size_t)Bb*Tt*Hh];
__device__ float g_qr[(size_t)Bb*NHh*Tt*HDd];
__device__ float g_kr[(size_t)Bb*NHh*Ss*HDd];
__device__ float g_vr[(size_t)Bb*NHh*Ss*HDd];
__device__ float g_attn[(size_t)Bb*Tt*Hh];
__device__ float g_norm[(size_t)Bb*Tt*Hh];

// ============================================================================
// SGEMM: C[m,n] = alpha * sum_k X[m,k] * W[n,k]  (torch Linear x @ W^T)
// 128x128x16 tiles, double-buffered smem, 8x8 per thread (4+4 split tiling)
// ============================================================================
__global__ __launch_bounds__(256, 2)
void gemm128(const float* __restrict__ X, const float* __restrict__ W,
             float* __restrict__ C, int M, int N, int K, float alpha)
{
    __shared__ float As[2][16][128];
    __shared__ float Bs[2][16][128];
    int tid = threadIdx.x;                 // 256
    int m0 = blockIdx.y * 128, n0 = blockIdx.x * 128;
    int tr = tid >> 4, tc = tid & 15;      // 16x16 thread grid

    // ldg mapping: each thread loads rows (arow, arow+64), 4 floats at col ac4*4
    int arow = tid >> 2, ac4 = tid & 3;
    const float* Ap = X + (size_t)(m0 + arow) * K + ac4 * 4;
    const float* Bp = W + (size_t)(n0 + arow) * K + ac4 * 4;

    float acc[8][8] = {};
    float4 a0, a1, b0, b1;

    // prologue: tile 0
    a0 = *(const float4*)(Ap);
    a1 = *(const float4*)(Ap + (size_t)64 * K);
    b0 = *(const float4*)(Bp);
    b1 = *(const float4*)(Bp + (size_t)64 * K);
    {
        int kk = ac4 * 4;
        As[0][kk+0][arow] = a0.x; As[0][kk+1][arow] = a0.y;
        As[0][kk+2][arow] = a0.z; As[0][kk+3][arow] = a0.w;
        As[0][kk+0][arow+64] = a1.x; As[0][kk+1][arow+64] = a1.y;
        As[0][kk+2][arow+64] = a1.z; As[0][kk+3][arow+64] = a1.w;
        Bs[0][kk+0][arow] = b0.x; Bs[0][kk+1][arow] = b0.y;
        Bs[0][kk+2][arow] = b0.z; Bs[0][kk+3][arow] = b0.w;
        Bs[0][kk+0][arow+64] = b1.x; Bs[0][kk+1][arow+64] = b1.y;
        Bs[0][kk+2][arow+64] = b1.z; Bs[0][kk+3][arow+64] = b1.w;
    }
    __syncthreads();

    int nt = K / 16;
    for (int t = 0; t < nt; t++) {
        int cur = t & 1;
        if (t + 1 < nt) {
            const float* ap = Ap + (t + 1) * 16;
            const float* bp = Bp + (t + 1) * 16;
            a0 = *(const float4*)(ap);
            a1 = *(const float4*)(ap + (size_t)64 * K);
            b0 = *(const float4*)(bp);
            b1 = *(const float4*)(bp + (size_t)64 * K);
        }
        #pragma unroll
        for (int kk = 0; kk < 16; kk++) {
            float4 aA = *(const float4*)&As[cur][kk][tr * 4];
            float4 aB = *(const float4*)&As[cur][kk][64 + tr * 4];
            float4 bA = *(const float4*)&Bs[cur][kk][tc * 4];
            float4 bB = *(const float4*)&Bs[cur][kk][64 + tc * 4];
            float av[8] = {aA.x, aA.y, aA.z, aA.w, aB.x, aB.y, aB.z, aB.w};
            float bv[8] = {bA.x, bA.y, bA.z, bA.w, bB.x, bB.y, bB.z, bB.w};
            #pragma unroll
            for (int i = 0; i < 8; i++)
                #pragma unroll
                for (int j = 0; j < 8; j++)
                    acc[i][j] += av[i] * bv[j];
        }
        if (t + 1 < nt) {
            int nxt = 1 - cur;
            int kk = ac4 * 4;
            As[nxt][kk+0][arow] = a0.x; As[nxt][kk+1][arow] = a0.y;
            As[nxt][kk+2][arow] = a0.z; As[nxt][kk+3][arow] = a0.w;
            As[nxt][kk+0][arow+64] = a1.x; As[nxt][kk+1][arow+64] = a1.y;
            As[nxt][kk+2][arow+64] = a1.z; As[nxt][kk+3][arow+64] = a1.w;
            Bs[nxt][kk+0][arow] = b0.x; Bs[nxt][kk+1][arow] = b0.y;
            Bs[nxt][kk+2][arow] = b0.z; Bs[nxt][kk+3][arow] = b0.w;
            Bs[nxt][kk+0][arow+64] = b1.x; Bs[nxt][kk+1][arow+64] = b1.y;
            Bs[nxt][kk+2][arow+64] = b1.z; Bs[nxt][kk+3][arow+64] = b1.w;
            __syncthreads();
        }
    }

    // epilogue: rows {m0+tr*4+i, m0+64+tr*4+i}, cols {n0+tc*4.., n0+64+tc*4..}
    #pragma unroll
    for (int i = 0; i < 8; i++) {
        int row = m0 + ((i < 4) ? (tr * 4 + i) : (64 + tr * 4 + i - 4));
        float4 lo = make_float4(acc[i][0]*alpha, acc[i][1]*alpha, acc[i][2]*alpha, acc[i][3]*alpha);
        float4 hi = make_float4(acc[i][4]*alpha, acc[i][5]*alpha, acc[i][6]*alpha, acc[i][7]*alpha);
        *(float4*)&C[(size_t)row * N + n0 + tc * 4]      = lo;
        *(float4*)&C[(size_t)row * N + n0 + 64 + tc * 4] = hi;
    }
}

// ---- PBC expand + RoPE: grid (S, NH, B), 64 threads ----
__global__ void rope_expand(const int* __restrict__ outcell)
{
    int s = blockIdx.x, h = blockIdx.y, b = blockIdx.z;
    int tid = threadIdx.x;
    int src = (s < Tt) ? s : outcell[b * Ee + (s - Tt)];
    const float* kp = g_kp + ((size_t)b * Tt + src) * Hh + h * HDd;
    const float* vp = g_vp + ((size_t)b * Tt + src) * Hh + h * HDd;
    float* krow = g_kr + (((size_t)b * NHh + h) * Ss + s) * HDd;
    float* vrow = g_vr + (((size_t)b * NHh + h) * Ss + s) * HDd;
    vrow[tid] = vp[tid];
    if (tid < 32) {
        float invf = __expf(-((float)(2 * tid) / 64.0f) * logf(10000.0f));
        float ang = (float)s * invf;
        float c, sn;
        __sincosf(ang, &sn, &c);
        // match fp32 reference precision: use accurate sin/cos
        c = cosf(ang); sn = sinf(ang);
        float x1 = kp[tid], x2 = kp[tid + 32];
        krow[tid]      = x1 * c - x2 * sn;
        krow[tid + 32] = x2 * c + x1 * sn;
        if (s < Tt) {
            const float* qp = g_qp + ((size_t)b * Tt + s) * Hh + h * HDd;
            float* qrow = g_qr + (((size_t)b * NHh + h) * Tt + s) * HDd;
            float y1 = qp[tid], y2 = qp[tid + 32];
            qrow[tid]      = y1 * c - y2 * sn;
            qrow[tid + 32] = y2 * c + y1 * sn;
        }
    }
}

// ============================================================================
// Flash-style attention: block = (q-tile of 16, head, batch); 256 threads
// thread (r, c): q-row r, k-cols c*4..c*4+3 per tile, out dims c*4..c*4+3
// ============================================================================
__global__ __launch_bounds__(256)
void attn2(const float* __restrict__ bias,
           const float* __restrict__ lw,
           const unsigned char* __restrict__ kpm,
           const unsigned char* __restrict__ em)
{
    int qt = blockIdx.x, h = blockIdx.y, b = blockIdx.z;
    int tid = threadIdx.x;
    int r = tid >> 4, c = tid & 15;
    int q0 = qt * QT;

    __shared__ float Qs[QT][64];
    __shared__ float KsT[64][68];   // transposed K tile: KsT[d][k]
    __shared__ float Vs[64][68];    // Vs[k][d], padded
    __shared__ float Ps[QT][68];    // probs (e * lw)

    {   // load Q tile: 256 float4s, one per thread
        int row = tid >> 4, d4 = tid & 15;
        ((float4*)Qs[row])[d4] =
            ((const float4*)(g_qr + (((size_t)b * NHh + h) * Tt + q0 + row) * 64))[d4];
    }

    const float* Kb = g_kr + ((size_t)b * NHh + h) * (size_t)Ss * 64;
    const float* Vb = g_vr + ((size_t)b * NHh + h) * (size_t)Ss * 64;
    const float* biasb = bias + (((size_t)b * NHh + h) * Tt + q0 + r) * (size_t)Ss;
    const float* lwb   = lw + ((size_t)b * Tt + q0 + r) * (size_t)Ss;

    float m = -INFINITY, l = 0.f;
    float4 acc = {0.f, 0.f, 0.f, 0.f};

    for (int kt = 0; kt < Ss / 64; kt++) {
        int k0 = kt * 64;
        __syncthreads();   // previous tile fully consumed before overwrite
        #pragma unroll
        for (int i = 0; i < 4; i++) {
            int idx = tid + i * 256;
            int kk = idx >> 4, d4 = idx & 15;
            float4 kv = ((const float4*)(Kb + (size_t)(k0 + kk) * 64))[d4];
            KsT[d4*4+0][kk] = kv.x; KsT[d4*4+1][kk] = kv.y;
            KsT[d4*4+2][kk] = kv.z; KsT[d4*4+3][kk] = kv.w;
            *(float4*)&Vs[kk][d4 * 4] = ((const float4*)(Vb + (size_t)(k0 + kk) * 64))[d4];
        }
        __syncthreads();

        // scores: s4[j] = Q[r]·K[c*4+j]
        float4 s4 = {0.f, 0.f, 0.f, 0.f};
        #pragma unroll
        for (int d4 = 0; d4 < 16; d4++) {
            float4 qv = *(const float4*)&Qs[r][d4 * 4];
            float4 kA = *(const float4*)&KsT[d4*4+0][c * 4];
            s4.x += qv.x * kA.x; s4.y += qv.x * kA.y; s4.z += qv.x * kA.z; s4.w += qv.x * kA.w;
            float4 kB = *(const float4*)&KsT[d4*4+1][c * 4];
            s4.x += qv.y * kB.x; s4.y += qv.y * kB.y; s4.z += qv.y * kB.z; s4.w += qv.y * kB.w;
            float4 kC = *(const float4*)&KsT[d4*4+2][c * 4];
            s4.x += qv.z * kC.x; s4.y += qv.z * kC.y; s4.z += qv.z * kC.z; s4.w += qv.z * kC.w;
            float4 kD = *(const float4*)&KsT[d4*4+3][c * 4];
            s4.x += qv.w * kD.x; s4.y += qv.w * kD.y; s4.z += qv.w * kD.z; s4.w += qv.w * kD.w;
        }

        float4 bv  = *(const float4*)(biasb + k0 + c * 4);
        float4 lwv = *(const float4*)(lwb + k0 + c * 4);
        uchar4 mv;
        if (k0 < Tt) mv = *(const uchar4*)(kpm + b * Tt + k0 + c * 4);
        else         mv = *(const uchar4*)(em + b * Ee + (k0 - Tt) + c * 4);
        s4.x = (lwv.x <= 1e-5f || mv.x) ? -INFINITY : s4.x + bv.x;
        s4.y = (lwv.y <= 1e-5f || mv.y) ? -INFINITY : s4.y + bv.y;
        s4.z = (lwv.z <= 1e-5f || mv.z) ? -INFINITY : s4.z + bv.z;
        s4.w = (lwv.w <= 1e-5f || mv.w) ? -INFINITY : s4.w + bv.w;

        // row max over 16 lanes
        float mt = fmaxf(fmaxf(s4.x, s4.y), fmaxf(s4.z, s4.w));
        #pragma unroll
        for (int off = 8; off > 0; off >>= 1)
            mt = fmaxf(mt, __shfl_xor_sync(0xffffffffu, mt, off, 16));

        float m_new = fmaxf(m, mt);
        float scale = (m_new > -INFINITY) ? __expf(m - m_new) : 1.0f;
        float mc = (m_new > -INFINITY) ? m_new : 0.0f;

        float e0 = __expf(s4.x - mc), e1 = __expf(s4.y - mc);
        float e2 = __expf(s4.z - mc), e3 = __expf(s4.w - mc);
        float es = e0 + e1 + e2 + e3;
        #pragma unroll
        for (int off = 8; off > 0; off >>= 1)
            es += __shfl_xor_sync(0xffffffffu, es, off, 16);
        l = l * scale + es;
        m = m_new;

        Ps[r][c*4+0] = e0 * lwv.x; Ps[r][c*4+1] = e1 * lwv.y;
        Ps[r][c*4+2] = e2 * lwv.z; Ps[r][c*4+3] = e3 * lwv.w;
        __syncwarp();

        acc.x *= scale; acc.y *= scale; acc.z *= scale; acc.w *= scale;

        // PV: out[d = c*4+j] += sum_k P[r][k] * V[k][d]
        #pragma unroll
        for (int k4 = 0; k4 < 16; k4++) {
            float4 pv = *(const float4*)&Ps[r][k4 * 4];
            float4 v0 = *(const float4*)&Vs[k4*4+0][c * 4];
            acc.x += pv.x * v0.x; acc.y += pv.x * v0.y; acc.z += pv.x * v0.z; acc.w += pv.x * v0.w;
            float4 v1 = *(const float4*)&Vs[k4*4+1][c * 4];
            acc.x += pv.y * v1.x; acc.y += pv.y * v1.y; acc.z += pv.y * v1.z; acc.w += pv.y * v1.w;
            float4 v2 = *(const float4*)&Vs[k4*4+2][c * 4];
            acc.x += pv.z * v2.x; acc.y += pv.z * v2.y; acc.z += pv.z * v2.z; acc.w += pv.z * v2.w;
            float4 v3 = *(const float4*)&Vs[k4*4+3][c * 4];
            acc.x += pv.w * v3.x; acc.y += pv.w * v3.y; acc.z += pv.w * v3.z; acc.w += pv.w * v3.w;
        }
    }

    float inv = 1.0f / l;
    float4 o = make_float4(acc.x * inv, acc.y * inv, acc.z * inv, acc.w * inv);
    *(float4*)&g_attn[((size_t)b * Tt + q0 + r) * Hh + h * 64 + c * 4] = o;
}

// ---- layernorm over H=1024 ----
__global__ void ln_kernel(const float* __restrict__ gamma, const float* __restrict__ beta)
{
    int row = blockIdx.x;
    int tid = threadIdx.x;
    const float* in = g_attn + (size_t)row * Hh;
    float* out = g_norm + (size_t)row * Hh;
    float s = 0.f, s2 = 0.f;
    float vals[4];
    #pragma unroll
    for (int i = 0; i < 4; i++) {
        float v = in[tid + i * 256];
        vals[i] = v; s += v; s2 += v * v;
    }
    __shared__ float rs[256], rs2[256];
    rs[tid] = s; rs2[tid] = s2;
    __syncthreads();
    for (int st = 128; st > 0; st >>= 1) {
        if (tid < st) { rs[tid] += rs[tid + st]; rs2[tid] += rs2[tid + st]; }
        __syncthreads();
    }
    float mean = rs[0] * (1.0f / Hh);
    float var  = rs2[0] * (1.0f / Hh) - mean * mean;
    float r = rsqrtf(var + 1e-5f);
    #pragma unroll
    for (int i = 0; i < 4; i++) {
        int col = tid + i * 256;
        out[col] = (vals[i] - mean) * r * gamma[col] + beta[col];
    }
}

extern "C" void kernel_launch(void* const* d_in, const int* in_sizes, int n_in,
                              void* d_out, int out_size)
{
    const float* x    = (const float*)d_in[0];
    const float* bias = (const float*)d_in[1];
    const float* lw   = (const float*)d_in[2];
    const unsigned char* kpm = (const unsigned char*)d_in[3];
    const int*   outcell = (const int*)d_in[4];
    const unsigned char* em  = (const unsigned char*)d_in[5];
    const float* wq   = (const float*)d_in[6];
    const float* wk   = (const float*)d_in[7];
    const float* wv   = (const float*)d_in[8];
    const float* wout = (const float*)d_in[9];
    const float* lng  = (const float*)d_in[10];
    const float* lnb  = (const float*)d_in[11];

    float *qp, *kp, *vp, *nrm;
    cudaGetSymbolAddress((void**)&qp,  g_qp);
    cudaGetSymbolAddress((void**)&kp,  g_kp);
    cudaGetSymbolAddress((void**)&vp,  g_vp);
    cudaGetSymbolAddress((void**)&nrm, g_norm);

    dim3 gg(Hh / 128, (Bb * Tt) / 128);
    gemm128<<<gg, 256>>>(x, wq, qp, Bb * Tt, Hh, Hh, 0.125f);
    gemm128<<<gg, 256>>>(x, wk, kp, Bb * Tt, Hh, Hh, 1.0f);
    gemm128<<<gg, 256>>>(x, wv, vp, Bb * Tt, Hh, Hh, 1.0f);
    rope_expand<<<dim3(Ss, NHh, Bb), 64>>>(outcell);
    attn2<<<dim3(Tt / QT, NHh, Bb), 256>>>(bias, lw, kpm, em);
    ln_kernel<<<Bb * Tt, 256>>>(lng, lnb);
    gemm128<<<gg, 256>>>(nrm, wout, (float*)d_out, Bb * Tt, Hh, Hh, 1.0f);
}

// round 3
// speedup vs baseline: 5.0992x; 1.6897x over previous
#include <cuda_runtime.h>
#include <math.h>

#define Bb 4
#define Tt 1024
#define Ee 512
#define Ss 1536
#define Hh 1024
#define NHh 16
#define HDd 64

// ---- scratch ----
__device__ float g_qp[(size_t)Bb*Tt*Hh];
__device__ float g_kp[(size_t)Bb*Tt*Hh];
__device__ float g_vp[(size_t)Bb*Tt*Hh];
__device__ float g_qrT[(size_t)Bb*NHh*HDd*Tt];   // [b][h][d][t]
__device__ float g_krT[(size_t)Bb*NHh*HDd*Ss];   // [b][h][d][s]
__device__ float g_vr [(size_t)Bb*NHh*Ss*HDd];   // [b][h][s][d]
__device__ float g_attn[(size_t)Bb*Tt*Hh];
__device__ float g_norm[(size_t)Bb*Tt*Hh];

// ============================================================================
// SGEMM 128x128x16, double-buffered, 8x8/thread.  C = alpha * X @ W^T
// qkv==1: blockIdx.z selects (wq,wk,wv)->(g_qp,g_kp,g_vp)
// ============================================================================
__global__ __launch_bounds__(256, 2)
void gemm128(const float* __restrict__ X,
             const float* __restrict__ W0, const float* __restrict__ W1,
             const float* __restrict__ W2,
             float* __restrict__ C0, float* __restrict__ C1, float* __restrict__ C2,
             int M, int N, int K, float alpha0)
{
    const float* W = (blockIdx.z == 0) ? W0 : (blockIdx.z == 1) ? W1 : W2;
    float*       C = (blockIdx.z == 0) ? C0 : (blockIdx.z == 1) ? C1 : C2;
    float alpha = (blockIdx.z == 0) ? alpha0 : 1.0f;

    __shared__ float As[2][16][128];
    __shared__ float Bs[2][16][128];
    int tid = threadIdx.x;
    int m0 = blockIdx.y * 128, n0 = blockIdx.x * 128;
    int tr = tid >> 4, tc = tid & 15;

    int arow = tid >> 2, ac4 = tid & 3;
    const float* Ap = X + (size_t)(m0 + arow) * K + ac4 * 4;
    const float* Bp = W + (size_t)(n0 + arow) * K + ac4 * 4;

    float acc[8][8] = {};
    float4 a0, a1, b0, b1;

    a0 = *(const float4*)(Ap);
    a1 = *(const float4*)(Ap + (size_t)64 * K);
    b0 = *(const float4*)(Bp);
    b1 = *(const float4*)(Bp + (size_t)64 * K);
    {
        int kk = ac4 * 4;
        As[0][kk+0][arow] = a0.x; As[0][kk+1][arow] = a0.y;
        As[0][kk+2][arow] = a0.z; As[0][kk+3][arow] = a0.w;
        As[0][kk+0][arow+64] = a1.x; As[0][kk+1][arow+64] = a1.y;
        As[0][kk+2][arow+64] = a1.z; As[0][kk+3][arow+64] = a1.w;
        Bs[0][kk+0][arow] = b0.x; Bs[0][kk+1][arow] = b0.y;
        Bs[0][kk+2][arow] = b0.z; Bs[0][kk+3][arow] = b0.w;
        Bs[0][kk+0][arow+64] = b1.x; Bs[0][kk+1][arow+64] = b1.y;
        Bs[0][kk+2][arow+64] = b1.z; Bs[0][kk+3][arow+64] = b1.w;
    }
    __syncthreads();

    int nt = K / 16;
    for (int t = 0; t < nt; t++) {
        int cur = t & 1;
        if (t + 1 < nt) {
            const float* ap = Ap + (t + 1) * 16;
            const float* bp = Bp + (t + 1) * 16;
            a0 = *(const float4*)(ap);
            a1 = *(const float4*)(ap + (size_t)64 * K);
            b0 = *(const float4*)(bp);
            b1 = *(const float4*)(bp + (size_t)64 * K);
        }
        #pragma unroll
        for (int kk = 0; kk < 16; kk++) {
            float4 aA = *(const float4*)&As[cur][kk][tr * 4];
            float4 aB = *(const float4*)&As[cur][kk][64 + tr * 4];
            float4 bA = *(const float4*)&Bs[cur][kk][tc * 4];
            float4 bB = *(const float4*)&Bs[cur][kk][64 + tc * 4];
            float av[8] = {aA.x, aA.y, aA.z, aA.w, aB.x, aB.y, aB.z, aB.w};
            float bv[8] = {bA.x, bA.y, bA.z, bA.w, bB.x, bB.y, bB.z, bB.w};
            #pragma unroll
            for (int i = 0; i < 8; i++)
                #pragma unroll
                for (int j = 0; j < 8; j++)
                    acc[i][j] += av[i] * bv[j];
        }
        if (t + 1 < nt) {
            int nxt = 1 - cur;
            int kk = ac4 * 4;
            As[nxt][kk+0][arow] = a0.x; As[nxt][kk+1][arow] = a0.y;
            As[nxt][kk+2][arow] = a0.z; As[nxt][kk+3][arow] = a0.w;
            As[nxt][kk+0][arow+64] = a1.x; As[nxt][kk+1][arow+64] = a1.y;
            As[nxt][kk+2][arow+64] = a1.z; As[nxt][kk+3][arow+64] = a1.w;
            Bs[nxt][kk+0][arow] = b0.x; Bs[nxt][kk+1][arow] = b0.y;
            Bs[nxt][kk+2][arow] = b0.z; Bs[nxt][kk+3][arow] = b0.w;
            Bs[nxt][kk+0][arow+64] = b1.x; Bs[nxt][kk+1][arow+64] = b1.y;
            Bs[nxt][kk+2][arow+64] = b1.z; Bs[nxt][kk+3][arow+64] = b1.w;
            __syncthreads();
        }
    }

    #pragma unroll
    for (int i = 0; i < 8; i++) {
        int row = m0 + ((i < 4) ? (tr * 4 + i) : (64 + tr * 4 + i - 4));
        float4 lo = make_float4(acc[i][0]*alpha, acc[i][1]*alpha, acc[i][2]*alpha, acc[i][3]*alpha);
        float4 hi = make_float4(acc[i][4]*alpha, acc[i][5]*alpha, acc[i][6]*alpha, acc[i][7]*alpha);
        *(float4*)&C[(size_t)row * N + n0 + tc * 4]      = lo;
        *(float4*)&C[(size_t)row * N + n0 + 64 + tc * 4] = hi;
    }
}

// ============================================================================
// PBC expand + RoPE + transpose.  grid (S/32, NH, B), 256 threads.
// Produces g_krT[b][h][d][s], g_qrT[b][h][d][t], g_vr[b][h][s][d].
// ============================================================================
__global__ __launch_bounds__(256)
void rope_expand_t(const int* __restrict__ outcell)
{
    __shared__ float sk[32][68];
    int s0 = blockIdx.x * 32, h = blockIdx.y, b = blockIdx.z;
    int t = threadIdx.x;
    size_t bh = (size_t)b * NHh + h;

    // ---- K tile: gathered load + V passthrough ----
    #pragma unroll
    for (int i = 0; i < 2; i++) {
        int idx = t + i * 256;          // 32 rows x 16 float4
        int r = idx >> 4, c4 = idx & 15;
        int s = s0 + r;
        int src = (s < Tt) ? s : outcell[b * Ee + (s - Tt)];
        const float* base = g_kp + ((size_t)b * Tt + src) * Hh + h * 64;
        float4 kv = ((const float4*)base)[c4];
        *(float4*)&sk[r][c4 * 4] = kv;
        const float* vbase = g_vp + ((size_t)b * Tt + src) * Hh + h * 64;
        float4 vv = ((const float4*)vbase)[c4];
        *(float4*)&g_vr[(bh * Ss + s) * 64 + c4 * 4] = vv;
    }
    __syncthreads();

    // ---- rope K + transposed store ----
    #pragma unroll
    for (int i = 0; i < 2; i++) {
        int idx = t + i * 256;          // 64 d-rows x 8 col groups
        int d = idx >> 3, cg = idx & 7;
        int j = d & 31;
        float invf = expf(-((float)(2 * j) / 64.0f) * logf(10000.0f));
        float4 o;
        float* op = (float*)&o;
        #pragma unroll
        for (int e = 0; e < 4; e++) {
            int sl = cg * 4 + e;
            float ang = (float)(s0 + sl) * invf;
            float c = cosf(ang), sn = sinf(ang);
            float v;
            if (d < 32) v = sk[sl][d] * c - sk[sl][d + 32] * sn;
            else        v = sk[sl][d] * c + sk[sl][d - 32] * sn;
            op[e] = v;
        }
        *(float4*)&g_krT[(bh * 64 + d) * Ss + s0 + cg * 4] = o;
    }

    if (s0 >= Tt) return;

    // ---- Q tile (no gather; s0+31 < T) ----
    __syncthreads();
    #pragma unroll
    for (int i = 0; i < 2; i++) {
        int idx = t + i * 256;
        int r = idx >> 4, c4 = idx & 15;
        const float* base = g_qp + ((size_t)b * Tt + s0 + r) * Hh + h * 64;
        *(float4*)&sk[r][c4 * 4] = ((const float4*)base)[c4];
    }
    __syncthreads();
    #pragma unroll
    for (int i = 0; i < 2; i++) {
        int idx = t + i * 256;
        int d = idx >> 3, cg = idx & 7;
        int j = d & 31;
        float invf = expf(-((float)(2 * j) / 64.0f) * logf(10000.0f));
        float4 o;
        float* op = (float*)&o;
        #pragma unroll
        for (int e = 0; e < 4; e++) {
            int sl = cg * 4 + e;
            float ang = (float)(s0 + sl) * invf;
            float c = cosf(ang), sn = sinf(ang);
            float v;
            if (d < 32) v = sk[sl][d] * c - sk[sl][d + 32] * sn;
            else        v = sk[sl][d] * c + sk[sl][d - 32] * sn;
            op[e] = v;
        }
        *(float4*)&g_qrT[(bh * 64 + d) * Tt + s0 + cg * 4] = o;
    }
}

// ============================================================================
// Flash attention: block = (32 q-rows, head, batch), 256 threads, K-tile 128.
// Warp w owns q rows w*4..w*4+3.  QK: 4q x 4k / thread.  PV: 4q x 2d / thread.
// ============================================================================
#define ATTN_SMEM_FLOATS (64*36 + 64*132 + 128*68 + 128*32)

__global__ __launch_bounds__(256, 2)
void attn3(const float* __restrict__ bias,
           const float* __restrict__ lw,
           const unsigned char* __restrict__ kpm,
           const unsigned char* __restrict__ em)
{
    extern __shared__ float sm[];
    float* Qs = sm;                    // [64][36]
    float* Ks = Qs + 64 * 36;          // [64][132]
    float* Vs = Ks + 64 * 132;         // [128][68]
    float* Ps = Vs + 128 * 68;         // [128][32], XOR-swizzled columns

    int qt = blockIdx.x, h = blockIdx.y, b = blockIdx.z;
    int t = threadIdx.x;
    int lane = t & 31, w = t >> 5;
    size_t bh = (size_t)b * NHh + h;
    int q0 = qt * 32;

    // stage Q tile (transposed source: g_qrT[bh][d][q])
    #pragma unroll
    for (int i = 0; i < 2; i++) {
        int idx = t + i * 256;         // 64 x 8 float4
        int d = idx >> 3, c4 = idx & 7;
        *(float4*)&Qs[d * 36 + c4 * 4] =
            *(const float4*)&g_qrT[(bh * 64 + d) * Tt + q0 + c4 * 4];
    }

    float m[4], l[4] = {0.f, 0.f, 0.f, 0.f};
    float acc[4][2] = {};
    #pragma unroll
    for (int i = 0; i < 4; i++) m[i] = -INFINITY;

    const float* biasb = bias + ((bh * Tt) + q0 + w * 4) * (size_t)Ss;
    const float* lwb   = lw + ((size_t)b * Tt + q0 + w * 4) * (size_t)Ss;

    for (int kt = 0; kt < Ss / 128; kt++) {
        int k0 = kt * 128;
        __syncthreads();
        // stage K (d-major) and V (s-major)
        #pragma unroll
        for (int i = 0; i < 8; i++) {
            int idx = t + i * 256;     // 2048 float4
            int d = idx >> 5, c4 = idx & 31;
            *(float4*)&Ks[d * 132 + c4 * 4] =
                *(const float4*)&g_krT[(bh * 64 + d) * Ss + k0 + c4 * 4];
            int kk = idx >> 4, d4 = idx & 15;
            *(float4*)&Vs[kk * 68 + d4 * 4] =
                *(const float4*)&g_vr[(bh * Ss + k0 + kk) * 64 + d4 * 4];
        }
        __syncthreads();

        // QK: s[i][j] = Q[w*4+i] . K[lane*4+j]
        float s[4][4] = {};
        #pragma unroll
        for (int d = 0; d < 64; d++) {
            float4 qv = *(const float4*)&Qs[d * 36 + w * 4];
            float4 kv = *(const float4*)&Ks[d * 132 + lane * 4];
            const float* qa = (const float*)&qv;
            const float* ka = (const float*)&kv;
            #pragma unroll
            for (int i = 0; i < 4; i++)
                #pragma unroll
                for (int j = 0; j < 4; j++)
                    s[i][j] += qa[i] * ka[j];
        }

        int kabs = k0 + lane * 4;
        uchar4 mk = (k0 < Tt) ? *(const uchar4*)(kpm + b * Tt + kabs)
                              : *(const uchar4*)(em + b * Ee + kabs - Tt);
        const unsigned char* mka = (const unsigned char*)&mk;

        float lwr[4][4];
        #pragma unroll
        for (int i = 0; i < 4; i++) {
            float4 bv  = *(const float4*)(biasb + (size_t)i * Ss + kabs);
            float4 lwv = *(const float4*)(lwb + (size_t)i * Ss + kabs);
            const float* ba = (const float*)&bv;
            const float* la = (const float*)&lwv;
            #pragma unroll
            for (int j = 0; j < 4; j++) {
                lwr[i][j] = la[j];
                s[i][j] = (la[j] <= 1e-5f || mka[j]) ? -INFINITY : s[i][j] + ba[j];
            }
        }

        // online softmax per q-row (replicated across warp)
        #pragma unroll
        for (int i = 0; i < 4; i++) {
            float mt = fmaxf(fmaxf(s[i][0], s[i][1]), fmaxf(s[i][2], s[i][3]));
            #pragma unroll
            for (int off = 16; off > 0; off >>= 1)
                mt = fmaxf(mt, __shfl_xor_sync(0xffffffffu, mt, off));
            float m_new = fmaxf(m[i], mt);
            float scale = (m_new > -INFINITY) ? __expf(m[i] - m_new) : 1.0f;
            float mc = (m_new > -INFINITY) ? m_new : 0.0f;
            float e0 = __expf(s[i][0] - mc), e1 = __expf(s[i][1] - mc);
            float e2 = __expf(s[i][2] - mc), e3 = __expf(s[i][3] - mc);
            float es = e0 + e1 + e2 + e3;
            #pragma unroll
            for (int off = 16; off > 0; off >>= 1)
                es += __shfl_xor_sync(0xffffffffu, es, off);
            l[i] = l[i] * scale + es;
            m[i] = m_new;
            acc[i][0] *= scale; acc[i][1] *= scale;
            s[i][0] = e0 * lwr[i][0]; s[i][1] = e1 * lwr[i][1];
            s[i][2] = e2 * lwr[i][2]; s[i][3] = e3 * lwr[i][3];
        }

        // write P transposed with XOR swizzle: Ps[k][ (w ^ ((k>>2)&7))*4 + i ]
        {
            int col = (w ^ (lane & 7)) * 4;   // k>>2 == lane for k = lane*4+j
            #pragma unroll
            for (int j = 0; j < 4; j++) {
                float4 pj = make_float4(s[0][j], s[1][j], s[2][j], s[3][j]);
                *(float4*)&Ps[(lane * 4 + j) * 32 + col] = pj;
            }
        }
        __syncwarp();

        // PV: acc[i][e] += sum_k P[k][q=w*4+i] * V[k][lane*2+e]
        int d0 = lane * 2;
        #pragma unroll 4
        for (int k = 0; k < 128; k++) {
            float4 p4 = *(const float4*)&Ps[k * 32 + ((w ^ ((k >> 2) & 7)) * 4)];
            float2 v2 = *(const float2*)&Vs[k * 68 + d0];
            const float* pa = (const float*)&p4;
            #pragma unroll
            for (int i = 0; i < 4; i++) {
                acc[i][0] += pa[i] * v2.x;
                acc[i][1] += pa[i] * v2.y;
            }
        }
        __syncwarp();
    }

    #pragma unroll
    for (int i = 0; i < 4; i++) {
        float inv = 1.0f / l[i];
        int q = q0 + w * 4 + i;
        float2 o = make_float2(acc[i][0] * inv, acc[i][1] * inv);
        *(float2*)&g_attn[((size_t)b * Tt + q) * Hh + h * 64 + lane * 2] = o;
    }
}

// ---- layernorm over H=1024 ----
__global__ void ln_kernel(const float* __restrict__ gamma, const float* __restrict__ beta)
{
    int row = blockIdx.x;
    int tid = threadIdx.x;
    const float* in = g_attn + (size_t)row * Hh;
    float* out = g_norm + (size_t)row * Hh;
    float s = 0.f, s2 = 0.f;
    float vals[4];
    #pragma unroll
    for (int i = 0; i < 4; i++) {
        float v = in[tid + i * 256];
        vals[i] = v; s += v; s2 += v * v;
    }
    __shared__ float rs[256], rs2[256];
    rs[tid] = s; rs2[tid] = s2;
    __syncthreads();
    for (int st = 128; st > 0; st >>= 1) {
        if (tid < st) { rs[tid] += rs[tid + st]; rs2[tid] += rs2[tid + st]; }
        __syncthreads();
    }
    float mean = rs[0] * (1.0f / Hh);
    float var  = rs2[0] * (1.0f / Hh) - mean * mean;
    float r = rsqrtf(var + 1e-5f);
    #pragma unroll
    for (int i = 0; i < 4; i++) {
        int col = tid + i * 256;
        out[col] = (vals[i] - mean) * r * gamma[col] + beta[col];
    }
}

extern "C" void kernel_launch(void* const* d_in, const int* in_sizes, int n_in,
                              void* d_out, int out_size)
{
    const float* x    = (const float*)d_in[0];
    const float* bias = (const float*)d_in[1];
    const float* lw   = (const float*)d_in[2];
    const unsigned char* kpm = (const unsigned char*)d_in[3];
    const int*   outcell = (const int*)d_in[4];
    const unsigned char* em  = (const unsigned char*)d_in[5];
    const float* wq   = (const float*)d_in[6];
    const float* wk   = (const float*)d_in[7];
    const float* wv   = (const float*)d_in[8];
    const float* wout = (const float*)d_in[9];
    const float* lng  = (const float*)d_in[10];
    const float* lnb  = (const float*)d_in[11];

    float *qp, *kp, *vp, *nrm;
    cudaGetSymbolAddress((void**)&qp,  g_qp);
    cudaGetSymbolAddress((void**)&kp,  g_kp);
    cudaGetSymbolAddress((void**)&vp,  g_vp);
    cudaGetSymbolAddress((void**)&nrm, g_norm);

    static int smem_set = 0;
    if (!smem_set) {
        cudaFuncSetAttribute(attn3, cudaFuncAttributeMaxDynamicSharedMemorySize,
                             ATTN_SMEM_FLOATS * 4);
        smem_set = 1;
    }

    // fused QKV projection (z selects weight/output)
    dim3 gq(Hh / 128, (Bb * Tt) / 128, 3);
    gemm128<<<gq, 256>>>(x, wq, wk, wv, qp, kp, vp, Bb * Tt, Hh, Hh, 0.125f);

    rope_expand_t<<<dim3(Ss / 32, NHh, Bb), 256>>>(outcell);

    attn3<<<dim3(Tt / 32, NHh, Bb), 256, ATTN_SMEM_FLOATS * 4>>>(bias, lw, kpm, em);

    ln_kernel<<<Bb * Tt, 256>>>(lng, lnb);

    dim3 gg(Hh / 128, (Bb * Tt) / 128, 1);
    gemm128<<<gg, 256>>>(nrm, wout, wout, wout, (float*)d_out, (float*)d_out,
                         (float*)d_out, Bb * Tt, Hh, Hh, 1.0f);
}

// round 4
// speedup vs baseline: 6.6607x; 1.3062x over previous
#include <cuda_runtime.h>
#include <cuda_bf16.h>
#include <math.h>

#define Bb 4
#define Tt 1024
#define Ee 512
#define Ss 1536
#define Hh 1024
#define NHh 16
#define HDd 64

// ---- scratch ----
__device__ float g_qp[(size_t)Bb*Tt*Hh];
__device__ float g_kp[(size_t)Bb*Tt*Hh];
__device__ float g_vp[(size_t)Bb*Tt*Hh];
__device__ float g_qr [(size_t)Bb*NHh*Tt*HDd];   // [b][h][q][d]
__device__ float g_krT[(size_t)Bb*NHh*HDd*Ss];   // [b][h][d][s]
__device__ float g_vr [(size_t)Bb*NHh*Ss*HDd];   // [b][h][s][d]
__device__ float g_attn[(size_t)Bb*Tt*Hh];
__device__ float g_norm[(size_t)Bb*Tt*Hh];

// ============================================================================
// SGEMM 128x128x16 (unchanged, known good)
// ============================================================================
__global__ __launch_bounds__(256, 2)
void gemm128(const float* __restrict__ X,
             const float* __restrict__ W0, const float* __restrict__ W1,
             const float* __restrict__ W2,
             float* __restrict__ C0, float* __restrict__ C1, float* __restrict__ C2,
             int M, int N, int K, float alpha0)
{
    const float* W = (blockIdx.z == 0) ? W0 : (blockIdx.z == 1) ? W1 : W2;
    float*       C = (blockIdx.z == 0) ? C0 : (blockIdx.z == 1) ? C1 : C2;
    float alpha = (blockIdx.z == 0) ? alpha0 : 1.0f;

    __shared__ float As[2][16][128];
    __shared__ float Bs[2][16][128];
    int tid = threadIdx.x;
    int m0 = blockIdx.y * 128, n0 = blockIdx.x * 128;
    int tr = tid >> 4, tc = tid & 15;

    int arow = tid >> 2, ac4 = tid & 3;
    const float* Ap = X + (size_t)(m0 + arow) * K + ac4 * 4;
    const float* Bp = W + (size_t)(n0 + arow) * K + ac4 * 4;

    float acc[8][8] = {};
    float4 a0, a1, b0, b1;

    a0 = *(const float4*)(Ap);
    a1 = *(const float4*)(Ap + (size_t)64 * K);
    b0 = *(const float4*)(Bp);
    b1 = *(const float4*)(Bp + (size_t)64 * K);
    {
        int kk = ac4 * 4;
        As[0][kk+0][arow] = a0.x; As[0][kk+1][arow] = a0.y;
        As[0][kk+2][arow] = a0.z; As[0][kk+3][arow] = a0.w;
        As[0][kk+0][arow+64] = a1.x; As[0][kk+1][arow+64] = a1.y;
        As[0][kk+2][arow+64] = a1.z; As[0][kk+3][arow+64] = a1.w;
        Bs[0][kk+0][arow] = b0.x; Bs[0][kk+1][arow] = b0.y;
        Bs[0][kk+2][arow] = b0.z; Bs[0][kk+3][arow] = b0.w;
        Bs[0][kk+0][arow+64] = b1.x; Bs[0][kk+1][arow+64] = b1.y;
        Bs[0][kk+2][arow+64] = b1.z; Bs[0][kk+3][arow+64] = b1.w;
    }
    __syncthreads();

    int nt = K / 16;
    for (int t = 0; t < nt; t++) {
        int cur = t & 1;
        if (t + 1 < nt) {
            const float* ap = Ap + (t + 1) * 16;
            const float* bp = Bp + (t + 1) * 16;
            a0 = *(const float4*)(ap);
            a1 = *(const float4*)(ap + (size_t)64 * K);
            b0 = *(const float4*)(bp);
            b1 = *(const float4*)(bp + (size_t)64 * K);
        }
        #pragma unroll
        for (int kk = 0; kk < 16; kk++) {
            float4 aA = *(const float4*)&As[cur][kk][tr * 4];
            float4 aB = *(const float4*)&As[cur][kk][64 + tr * 4];
            float4 bA = *(const float4*)&Bs[cur][kk][tc * 4];
            float4 bB = *(const float4*)&Bs[cur][kk][64 + tc * 4];
            float av[8] = {aA.x, aA.y, aA.z, aA.w, aB.x, aB.y, aB.z, aB.w};
            float bv[8] = {bA.x, bA.y, bA.z, bA.w, bB.x, bB.y, bB.z, bB.w};
            #pragma unroll
            for (int i = 0; i < 8; i++)
                #pragma unroll
                for (int j = 0; j < 8; j++)
                    acc[i][j] += av[i] * bv[j];
        }
        if (t + 1 < nt) {
            int nxt = 1 - cur;
            int kk = ac4 * 4;
            As[nxt][kk+0][arow] = a0.x; As[nxt][kk+1][arow] = a0.y;
            As[nxt][kk+2][arow] = a0.z; As[nxt][kk+3][arow] = a0.w;
            As[nxt][kk+0][arow+64] = a1.x; As[nxt][kk+1][arow+64] = a1.y;
            As[nxt][kk+2][arow+64] = a1.z; As[nxt][kk+3][arow+64] = a1.w;
            Bs[nxt][kk+0][arow] = b0.x; Bs[nxt][kk+1][arow] = b0.y;
            Bs[nxt][kk+2][arow] = b0.z; Bs[nxt][kk+3][arow] = b0.w;
            Bs[nxt][kk+0][arow+64] = b1.x; Bs[nxt][kk+1][arow+64] = b1.y;
            Bs[nxt][kk+2][arow+64] = b1.z; Bs[nxt][kk+3][arow+64] = b1.w;
            __syncthreads();
        }
    }

    #pragma unroll
    for (int i = 0; i < 8; i++) {
        int row = m0 + ((i < 4) ? (tr * 4 + i) : (64 + tr * 4 + i - 4));
        float4 lo = make_float4(acc[i][0]*alpha, acc[i][1]*alpha, acc[i][2]*alpha, acc[i][3]*alpha);
        float4 hi = make_float4(acc[i][4]*alpha, acc[i][5]*alpha, acc[i][6]*alpha, acc[i][7]*alpha);
        *(float4*)&C[(size_t)row * N + n0 + tc * 4]      = lo;
        *(float4*)&C[(size_t)row * N + n0 + 64 + tc * 4] = hi;
    }
}

// ============================================================================
// PBC expand + RoPE.  K -> d-major (g_krT), V -> s-major (g_vr), Q -> q-major.
// ============================================================================
__global__ __launch_bounds__(256)
void rope_expand_t(const int* __restrict__ outcell)
{
    __shared__ float sk[32][68];
    int s0 = blockIdx.x * 32, h = blockIdx.y, b = blockIdx.z;
    int t = threadIdx.x;
    size_t bh = (size_t)b * NHh + h;

    #pragma unroll
    for (int i = 0; i < 2; i++) {
        int idx = t + i * 256;
        int r = idx >> 4, c4 = idx & 15;
        int s = s0 + r;
        int src = (s < Tt) ? s : outcell[b * Ee + (s - Tt)];
        const float* base = g_kp + ((size_t)b * Tt + src) * Hh + h * 64;
        float4 kv = ((const float4*)base)[c4];
        *(float4*)&sk[r][c4 * 4] = kv;
        const float* vbase = g_vp + ((size_t)b * Tt + src) * Hh + h * 64;
        float4 vv = ((const float4*)vbase)[c4];
        *(float4*)&g_vr[(bh * Ss + s) * 64 + c4 * 4] = vv;
    }
    __syncthreads();

    // rope K + transposed store (d-major)
    #pragma unroll
    for (int i = 0; i < 2; i++) {
        int idx = t + i * 256;
        int d = idx >> 3, cg = idx & 7;
        int j = d & 31;
        float invf = expf(-((float)(2 * j) / 64.0f) * logf(10000.0f));
        float4 o;
        float* op = (float*)&o;
        #pragma unroll
        for (int e = 0; e < 4; e++) {
            int sl = cg * 4 + e;
            float ang = (float)(s0 + sl) * invf;
            float c = cosf(ang), sn = sinf(ang);
            float v;
            if (d < 32) v = sk[sl][d] * c - sk[sl][d + 32] * sn;
            else        v = sk[sl][d] * c + sk[sl][d - 32] * sn;
            op[e] = v;
        }
        *(float4*)&g_krT[(bh * 64 + d) * Ss + s0 + cg * 4] = o;
    }

    if (s0 >= Tt) return;

    // Q tile: rope, store q-major
    __syncthreads();
    #pragma unroll
    for (int i = 0; i < 2; i++) {
        int idx = t + i * 256;
        int r = idx >> 4, c4 = idx & 15;
        const float* base = g_qp + ((size_t)b * Tt + s0 + r) * Hh + h * 64;
        *(float4*)&sk[r][c4 * 4] = ((const float4*)base)[c4];
    }
    __syncthreads();
    #pragma unroll
    for (int i = 0; i < 2; i++) {
        int idx = t + i * 256;
        int r = idx >> 4, c4 = idx & 15;
        float4 o;
        float* op = (float*)&o;
        #pragma unroll
        for (int e = 0; e < 4; e++) {
            int d = c4 * 4 + e;
            int j = d & 31;
            float invf = expf(-((float)(2 * j) / 64.0f) * logf(10000.0f));
            float ang = (float)(s0 + r) * invf;
            float c = cosf(ang), sn = sinf(ang);
            float v;
            if (d < 32) v = sk[r][d] * c - sk[r][d + 32] * sn;
            else        v = sk[r][d] * c + sk[r][d - 32] * sn;
            op[e] = v;
        }
        *(float4*)&g_qr[((bh * Tt) + s0 + r) * 64 + c4 * 4] = o;
    }
}

// ============================================================================
// Tensor-core flash attention (split-bf16 3xMMA).
// block: 128 q x (loop) 64 k, 8 warps (16 q each). m16n8k16 bf16 mma.
// ============================================================================
#define ATT_SMEM_U32 (2*128*36 + 4*32*72 + 2*8*16*36)

__device__ __forceinline__ void mma_bf16(float c[4],
    unsigned a0, unsigned a1, unsigned a2, unsigned a3,
    unsigned b0, unsigned b1)
{
    asm volatile(
        "mma.sync.aligned.m16n8k16.row.col.f32.bf16.bf16.f32 "
        "{%0,%1,%2,%3}, {%4,%5,%6,%7}, {%8,%9}, {%0,%1,%2,%3};\n"
        : "+f"(c[0]), "+f"(c[1]), "+f"(c[2]), "+f"(c[3])
        : "r"(a0), "r"(a1), "r"(a2), "r"(a3), "r"(b0), "r"(b1));
}

__device__ __forceinline__ void split2(float x, float y, unsigned &hi, unsigned &lo)
{
    __nv_bfloat16 hx = __float2bfloat16_rn(x);
    __nv_bfloat16 hy = __float2bfloat16_rn(y);
    __nv_bfloat16 lx = __float2bfloat16_rn(x - __bfloat162float(hx));
    __nv_bfloat16 ly = __float2bfloat16_rn(y - __bfloat162float(hy));
    hi = ((unsigned)__bfloat16_as_ushort(hy) << 16) | (unsigned)__bfloat16_as_ushort(hx);
    lo = ((unsigned)__bfloat16_as_ushort(ly) << 16) | (unsigned)__bfloat16_as_ushort(lx);
}

__global__ __launch_bounds__(256)
void attn4(const float* __restrict__ bias, const float* __restrict__ lw,
           const unsigned char* __restrict__ kpm, const unsigned char* __restrict__ em)
{
    extern __shared__ unsigned su[];
    unsigned* Qh = su;                  // [128][36]
    unsigned* Ql = Qh + 128 * 36;
    unsigned* Kh = Ql + 128 * 36;       // [32][72]  (d2 x k)
    unsigned* Kl = Kh + 32 * 72;
    unsigned* Vh = Kl + 32 * 72;        // [32][72]  (k2 x d)
    unsigned* Vl = Vh + 32 * 72;
    unsigned* Ph = Vl + 32 * 72;        // per-warp [16][36]
    unsigned* Pl = Ph + 8 * 16 * 36;

    int t = threadIdx.x;
    int lane = t & 31, w = t >> 5;
    int g = lane >> 2, t4 = lane & 3;
    int qt = blockIdx.x, h = blockIdx.y, b = blockIdx.z;
    size_t bh = (size_t)b * NHh + h;
    int q0 = qt * 128;

    // ---- stage Q (packed bf16 pairs along d) ----
    #pragma unroll
    for (int i = 0; i < 16; i++) {
        int idx = t + i * 256;
        int q = idx >> 5, d2 = idx & 31;
        float2 v = *(const float2*)&g_qr[((bh * Tt) + q0 + q) * 64 + 2 * d2];
        unsigned hi, lo; split2(v.x, v.y, hi, lo);
        Qh[q * 36 + d2] = hi; Ql[q * 36 + d2] = lo;
    }

    float m0 = -INFINITY, m1 = -INFINITY, l0 = 0.f, l1 = 0.f;
    float oacc[8][4] = {};

    const float* biasr = bias + ((bh * Tt) + q0 + w * 16 + g) * (size_t)Ss;
    const float* lwr   = lw + ((size_t)b * Tt + q0 + w * 16 + g) * (size_t)Ss;
    unsigned* Phw = Ph + w * 16 * 36;
    unsigned* Plw = Pl + w * 16 * 36;

    for (int kt = 0; kt < Ss / 64; kt++) {
        int k0 = kt * 64;
        __syncthreads();
        // ---- stage K (d-major pairs) and V (key-major pairs) ----
        #pragma unroll
        for (int i = 0; i < 8; i++) {
            int idx = t + i * 256;
            int r = idx >> 6, c = idx & 63;     // r: d2 or k2, c: k or d
            float ka = g_krT[(bh * 64 + 2 * r) * (size_t)Ss + k0 + c];
            float kb = g_krT[(bh * 64 + 2 * r + 1) * (size_t)Ss + k0 + c];
            unsigned hi, lo; split2(ka, kb, hi, lo);
            Kh[r * 72 + c] = hi; Kl[r * 72 + c] = lo;
            float va = g_vr[(bh * Ss + k0 + 2 * r) * 64 + c];
            float vb = g_vr[(bh * Ss + k0 + 2 * r + 1) * 64 + c];
            unsigned vhi, vlo; split2(va, vb, vhi, vlo);
            Vh[r * 72 + c] = vhi; Vl[r * 72 + c] = vlo;
        }
        __syncthreads();

        // ---- QK: scores 16q x 64k per warp ----
        float sc[8][4];
        #pragma unroll
        for (int ns = 0; ns < 8; ns++)
            #pragma unroll
            for (int j = 0; j < 4; j++) sc[ns][j] = 0.f;

        int qb = w * 16;
        #pragma unroll
        for (int dc = 0; dc < 4; dc++) {
            unsigned ah0 = Qh[(qb + g) * 36 + dc * 8 + t4];
            unsigned ah1 = Qh[(qb + g + 8) * 36 + dc * 8 + t4];
            unsigned ah2 = Qh[(qb + g) * 36 + dc * 8 + t4 + 4];
            unsigned ah3 = Qh[(qb + g + 8) * 36 + dc * 8 + t4 + 4];
            unsigned al0 = Ql[(qb + g) * 36 + dc * 8 + t4];
            unsigned al1 = Ql[(qb + g + 8) * 36 + dc * 8 + t4];
            unsigned al2 = Ql[(qb + g) * 36 + dc * 8 + t4 + 4];
            unsigned al3 = Ql[(qb + g + 8) * 36 + dc * 8 + t4 + 4];
            #pragma unroll
            for (int ns = 0; ns < 8; ns++) {
                unsigned bh0 = Kh[(dc * 8 + t4) * 72 + ns * 8 + g];
                unsigned bh1 = Kh[(dc * 8 + t4 + 4) * 72 + ns * 8 + g];
                unsigned bl0 = Kl[(dc * 8 + t4) * 72 + ns * 8 + g];
                unsigned bl1 = Kl[(dc * 8 + t4 + 4) * 72 + ns * 8 + g];
                mma_bf16(sc[ns], ah0, ah1, ah2, ah3, bh0, bh1);
                mma_bf16(sc[ns], ah0, ah1, ah2, ah3, bl0, bl1);
                mma_bf16(sc[ns], al0, al1, al2, al3, bh0, bh1);
            }
        }

        // ---- bias + masks ----
        float lwv[8][4];
        float tm0 = -INFINITY, tm1 = -INFINITY;
        #pragma unroll
        for (int ns = 0; ns < 8; ns++) {
            int kb = k0 + ns * 8 + 2 * t4;
            float2 b0v = *(const float2*)(biasr + kb);
            float2 b1v = *(const float2*)(biasr + 8 * (size_t)Ss + kb);
            float2 l0v = *(const float2*)(lwr + kb);
            float2 l1v = *(const float2*)(lwr + 8 * (size_t)Ss + kb);
            unsigned char ma0, ma1;
            if (k0 < Tt) { ma0 = kpm[b * Tt + kb]; ma1 = kpm[b * Tt + kb + 1]; }
            else         { ma0 = em[b * Ee + kb - Tt]; ma1 = em[b * Ee + kb - Tt + 1]; }
            sc[ns][0] = (l0v.x <= 1e-5f || ma0) ? -INFINITY : sc[ns][0] + b0v.x;
            sc[ns][1] = (l0v.y <= 1e-5f || ma1) ? -INFINITY : sc[ns][1] + b0v.y;
            sc[ns][2] = (l1v.x <= 1e-5f || ma0) ? -INFINITY : sc[ns][2] + b1v.x;
            sc[ns][3] = (l1v.y <= 1e-5f || ma1) ? -INFINITY : sc[ns][3] + b1v.y;
            lwv[ns][0] = l0v.x; lwv[ns][1] = l0v.y;
            lwv[ns][2] = l1v.x; lwv[ns][3] = l1v.y;
            tm0 = fmaxf(tm0, fmaxf(sc[ns][0], sc[ns][1]));
            tm1 = fmaxf(tm1, fmaxf(sc[ns][2], sc[ns][3]));
        }
        // reduce across the 4 lanes owning each row
        tm0 = fmaxf(tm0, __shfl_xor_sync(0xffffffffu, tm0, 1));
        tm0 = fmaxf(tm0, __shfl_xor_sync(0xffffffffu, tm0, 2));
        tm1 = fmaxf(tm1, __shfl_xor_sync(0xffffffffu, tm1, 1));
        tm1 = fmaxf(tm1, __shfl_xor_sync(0xffffffffu, tm1, 2));

        float mn0 = fmaxf(m0, tm0);
        float mn1 = fmaxf(m1, tm1);
        float scl0 = (mn0 > -INFINITY) ? __expf(m0 - mn0) : 1.0f;
        float scl1 = (mn1 > -INFINITY) ? __expf(m1 - mn1) : 1.0f;
        float mc0 = (mn0 > -INFINITY) ? mn0 : 0.0f;
        float mc1 = (mn1 > -INFINITY) ? mn1 : 0.0f;

        float es0 = 0.f, es1 = 0.f;
        #pragma unroll
        for (int ns = 0; ns < 8; ns++) {
            float e0 = __expf(sc[ns][0] - mc0);
            float e1 = __expf(sc[ns][1] - mc0);
            float e2 = __expf(sc[ns][2] - mc1);
            float e3 = __expf(sc[ns][3] - mc1);
            es0 += e0 + e1; es1 += e2 + e3;
            unsigned hi, lo;
            split2(e0 * lwv[ns][0], e1 * lwv[ns][1], hi, lo);
            Phw[g * 36 + ns * 4 + t4] = hi;
            Plw[g * 36 + ns * 4 + t4] = lo;
            split2(e2 * lwv[ns][2], e3 * lwv[ns][3], hi, lo);
            Phw[(g + 8) * 36 + ns * 4 + t4] = hi;
            Plw[(g + 8) * 36 + ns * 4 + t4] = lo;
        }
        es0 += __shfl_xor_sync(0xffffffffu, es0, 1);
        es0 += __shfl_xor_sync(0xffffffffu, es0, 2);
        es1 += __shfl_xor_sync(0xffffffffu, es1, 1);
        es1 += __shfl_xor_sync(0xffffffffu, es1, 2);
        l0 = l0 * scl0 + es0; m0 = mn0;
        l1 = l1 * scl1 + es1; m1 = mn1;

        #pragma unroll
        for (int ns = 0; ns < 8; ns++) {
            oacc[ns][0] *= scl0; oacc[ns][1] *= scl0;
            oacc[ns][2] *= scl1; oacc[ns][3] *= scl1;
        }
        __syncwarp();

        // ---- PV: out 16q x 64d per warp ----
        #pragma unroll
        for (int kc = 0; kc < 4; kc++) {
            unsigned ah0 = Phw[g * 36 + kc * 8 + t4];
            unsigned ah1 = Phw[(g + 8) * 36 + kc * 8 + t4];
            unsigned ah2 = Phw[g * 36 + kc * 8 + t4 + 4];
            unsigned ah3 = Phw[(g + 8) * 36 + kc * 8 + t4 + 4];
            unsigned al0 = Plw[g * 36 + kc * 8 + t4];
            unsigned al1 = Plw[(g + 8) * 36 + kc * 8 + t4];
            unsigned al2 = Plw[g * 36 + kc * 8 + t4 + 4];
            unsigned al3 = Plw[(g + 8) * 36 + kc * 8 + t4 + 4];
            #pragma unroll
            for (int ns = 0; ns < 8; ns++) {
                unsigned b0 = Vh[(kc * 8 + t4) * 72 + ns * 8 + g];
                unsigned b1 = Vh[(kc * 8 + t4 + 4) * 72 + ns * 8 + g];
                unsigned c0 = Vl[(kc * 8 + t4) * 72 + ns * 8 + g];
                unsigned c1 = Vl[(kc * 8 + t4 + 4) * 72 + ns * 8 + g];
                mma_bf16(oacc[ns], ah0, ah1, ah2, ah3, b0, b1);
                mma_bf16(oacc[ns], ah0, ah1, ah2, ah3, c0, c1);
                mma_bf16(oacc[ns], al0, al1, al2, al3, b0, b1);
            }
        }
    }

    float i0 = 1.0f / l0, i1 = 1.0f / l1;
    int r0 = q0 + w * 16 + g;
    #pragma unroll
    for (int ns = 0; ns < 8; ns++) {
        float2 o0 = make_float2(oacc[ns][0] * i0, oacc[ns][1] * i0);
        float2 o1 = make_float2(oacc[ns][2] * i1, oacc[ns][3] * i1);
        *(float2*)&g_attn[((size_t)b * Tt + r0) * Hh + h * 64 + ns * 8 + 2 * t4] = o0;
        *(float2*)&g_attn[((size_t)b * Tt + r0 + 8) * Hh + h * 64 + ns * 8 + 2 * t4] = o1;
    }
}

// ---- layernorm over H=1024 ----
__global__ void ln_kernel(const float* __restrict__ gamma, const float* __restrict__ beta)
{
    int row = blockIdx.x;
    int tid = threadIdx.x;
    const float* in = g_attn + (size_t)row * Hh;
    float* out = g_norm + (size_t)row * Hh;
    float s = 0.f, s2 = 0.f;
    float vals[4];
    #pragma unroll
    for (int i = 0; i < 4; i++) {
        float v = in[tid + i * 256];
        vals[i] = v; s += v; s2 += v * v;
    }
    __shared__ float rs[256], rs2[256];
    rs[tid] = s; rs2[tid] = s2;
    __syncthreads();
    for (int st = 128; st > 0; st >>= 1) {
        if (tid < st) { rs[tid] += rs[tid + st]; rs2[tid] += rs2[tid + st]; }
        __syncthreads();
    }
    float mean = rs[0] * (1.0f / Hh);
    float var  = rs2[0] * (1.0f / Hh) - mean * mean;
    float r = rsqrtf(var + 1e-5f);
    #pragma unroll
    for (int i = 0; i < 4; i++) {
        int col = tid + i * 256;
        out[col] = (vals[i] - mean) * r * gamma[col] + beta[col];
    }
}

extern "C" void kernel_launch(void* const* d_in, const int* in_sizes, int n_in,
                              void* d_out, int out_size)
{
    const float* x    = (const float*)d_in[0];
    const float* bias = (const float*)d_in[1];
    const float* lw   = (const float*)d_in[2];
    const unsigned char* kpm = (const unsigned char*)d_in[3];
    const int*   outcell = (const int*)d_in[4];
    const unsigned char* em  = (const unsigned char*)d_in[5];
    const float* wq   = (const float*)d_in[6];
    const float* wk   = (const float*)d_in[7];
    const float* wv   = (const float*)d_in[8];
    const float* wout = (const float*)d_in[9];
    const float* lng  = (const float*)d_in[10];
    const float* lnb  = (const float*)d_in[11];

    float *qp, *kp, *vp, *nrm;
    cudaGetSymbolAddress((void**)&qp,  g_qp);
    cudaGetSymbolAddress((void**)&kp,  g_kp);
    cudaGetSymbolAddress((void**)&vp,  g_vp);
    cudaGetSymbolAddress((void**)&nrm, g_norm);

    static int smem_set = 0;
    if (!smem_set) {
        cudaFuncSetAttribute(attn4, cudaFuncAttributeMaxDynamicSharedMemorySize,
                             ATT_SMEM_U32 * 4);
        smem_set = 1;
    }

    dim3 gq(Hh / 128, (Bb * Tt) / 128, 3);
    gemm128<<<gq, 256>>>(x, wq, wk, wv, qp, kp, vp, Bb * Tt, Hh, Hh, 0.125f);

    rope_expand_t<<<dim3(Ss / 32, NHh, Bb), 256>>>(outcell);

    attn4<<<dim3(Tt / 128, NHh, Bb), 256, ATT_SMEM_U32 * 4>>>(bias, lw, kpm, em);

    ln_kernel<<<Bb * Tt, 256>>>(lng, lnb);

    dim3 gg(Hh / 128, (Bb * Tt) / 128, 1);
    gemm128<<<gg, 256>>>(nrm, wout, wout, wout, (float*)d_out, (float*)d_out,
                         (float*)d_out, Bb * Tt, Hh, Hh, 1.0f);
}

// round 6
// speedup vs baseline: 9.0098x; 1.3527x over previous
#include <cuda_runtime.h>
#include <cuda_bf16.h>
#include <math.h>
#include <stdint.h>

#define Bb 4
#define Tt 1024
#define Ee 512
#define Ss 1536
#define Hh 1024
#define NHh 16
#define HDd 64

// ---- scratch ----
__device__ float    g_qp[(size_t)Bb*Tt*Hh];
__device__ float    g_kp[(size_t)Bb*Tt*Hh];
__device__ float    g_vp[(size_t)Bb*Tt*Hh];
__device__ float    g_attn[(size_t)Bb*Tt*Hh];
__device__ unsigned g_xh[(size_t)Bb*Tt*Hh/2], g_xl[(size_t)Bb*Tt*Hh/2];
__device__ unsigned g_wqh[Hh*Hh/2], g_wql[Hh*Hh/2];
__device__ unsigned g_wkh[Hh*Hh/2], g_wkl[Hh*Hh/2];
__device__ unsigned g_wvh[Hh*Hh/2], g_wvl[Hh*Hh/2];
__device__ unsigned g_woh[Hh*Hh/2], g_wol[Hh*Hh/2];
__device__ unsigned g_nh[(size_t)Bb*Tt*Hh/2], g_nl[(size_t)Bb*Tt*Hh/2];
__device__ unsigned g_qh[(size_t)Bb*NHh*Tt*32], g_ql[(size_t)Bb*NHh*Tt*32];   // [bh][q][d2]
__device__ unsigned g_kh[(size_t)Bb*NHh*32*Ss], g_kl[(size_t)Bb*NHh*32*Ss];   // [bh][d2][s]
__device__ unsigned g_vh[(size_t)Bb*NHh*768*64], g_vl[(size_t)Bb*NHh*768*64]; // [bh][s2][d]

// ======================= helpers ============================================
__device__ __forceinline__ uint32_t smem_to_u32(const void* p) {
    uint32_t a;
    asm("{ .reg .u64 tmp; cvta.to.shared.u64 tmp, %1; cvt.u32.u64 %0, tmp; }"
        : "=r"(a) : "l"(p));
    return a;
}

__device__ __forceinline__ void mma_bf16(float c[4],
    unsigned a0, unsigned a1, unsigned a2, unsigned a3, unsigned b0, unsigned b1)
{
    asm volatile(
        "mma.sync.aligned.m16n8k16.row.col.f32.bf16.bf16.f32 "
        "{%0,%1,%2,%3}, {%4,%5,%6,%7}, {%8,%9}, {%0,%1,%2,%3};\n"
        : "+f"(c[0]), "+f"(c[1]), "+f"(c[2]), "+f"(c[3])
        : "r"(a0), "r"(a1), "r"(a2), "r"(a3), "r"(b0), "r"(b1));
}

#define LDSM_X4(r0, r1, r2, r3, a) \
    asm volatile("ldmatrix.sync.aligned.m8n8.x4.shared.b16 {%0,%1,%2,%3}, [%4];" \
                 : "=r"(r0), "=r"(r1), "=r"(r2), "=r"(r3) : "r"(a))

__device__ __forceinline__ void split2(float x, float y, unsigned &hi, unsigned &lo)
{
    __nv_bfloat16 hx = __float2bfloat16_rn(x);
    __nv_bfloat16 hy = __float2bfloat16_rn(y);
    __nv_bfloat16 lx = __float2bfloat16_rn(x - __bfloat162float(hx));
    __nv_bfloat16 ly = __float2bfloat16_rn(y - __bfloat162float(hy));
    hi = ((unsigned)__bfloat16_as_ushort(hy) << 16) | (unsigned)__bfloat16_as_ushort(hx);
    lo = ((unsigned)__bfloat16_as_ushort(ly) << 16) | (unsigned)__bfloat16_as_ushort(lx);
}

// ======================= split fp32 -> packed bf16 hi/lo ====================
__global__ void splitk(const float* __restrict__ in, unsigned* __restrict__ hi,
                       unsigned* __restrict__ lo, int npairs, float alpha)
{
    int i = blockIdx.x * 256 + threadIdx.x;
    if (i < npairs) {
        float2 v = ((const float2*)in)[i];
        unsigned h, l;
        split2(v.x * alpha, v.y * alpha, h, l);
        hi[i] = h; lo[i] = l;
    }
}

// ======================= mma.sync GEMM: C = X @ W^T (split-bf16 x3) =========
// X packed [M][K2] u32 pairs, W packed [N][K2].  Block tile 128x128, chunk K=64.
// 8 warps: warp (wm= w>>2, wn= w&3) computes 64x32.
#define GM_STRIDE 36
#define GM_SMEM_BYTES (4 * 128 * GM_STRIDE * 4)

__global__ __launch_bounds__(256)
void gemm_mma(const unsigned* __restrict__ Xh, const unsigned* __restrict__ Xl,
              const unsigned* __restrict__ Wh0, const unsigned* __restrict__ Wl0,
              const unsigned* __restrict__ Wh1, const unsigned* __restrict__ Wl1,
              const unsigned* __restrict__ Wh2, const unsigned* __restrict__ Wl2,
              float* __restrict__ C0, float* __restrict__ C1, float* __restrict__ C2,
              int N, int K)
{
    const unsigned* Wh = (blockIdx.z == 0) ? Wh0 : (blockIdx.z == 1) ? Wh1 : Wh2;
    const unsigned* Wl = (blockIdx.z == 0) ? Wl0 : (blockIdx.z == 1) ? Wl1 : Wl2;
    float*          C  = (blockIdx.z == 0) ? C0  : (blockIdx.z == 1) ? C1  : C2;

    extern __shared__ unsigned gs[];
    unsigned* Ah = gs;
    unsigned* Al = Ah + 128 * GM_STRIDE;
    unsigned* Bh = Al + 128 * GM_STRIDE;
    unsigned* Bl = Bh + 128 * GM_STRIDE;

    int t = threadIdx.x, lane = t & 31, w = t >> 5;
    int m0 = blockIdx.y * 128, n0 = blockIdx.x * 128;
    int K2 = K / 2;
    int wm = w >> 2, wn = w & 3;

    uint32_t sAh = smem_to_u32(Ah), sAl = smem_to_u32(Al);
    uint32_t sBh = smem_to_u32(Bh), sBl = smem_to_u32(Bl);

    // fragment smem addresses (u32 offsets scaled to bytes)
    int arow = wm * 64 + (lane & 15);
    uint32_t aoff = ((lane >> 4) * 4) * 4;            // +16B for k8-15 half
    int brow_base = wn * 32 + (lane & 7) + ((lane >> 3) & 1) * 8;
    uint32_t boff = ((lane >> 4) * 4) * 4;

    float acc[4][4][4] = {};

    int nch = K / 64;
    for (int ch = 0; ch < nch; ch++) {
        int kc = ch * 32;                              // u32 offset into row
        __syncthreads();
        #pragma unroll
        for (int i = 0; i < 4; i++) {
            int idx = t + i * 256;                     // 1024: 128 rows x 8 float4
            int r = idx >> 3, c4 = idx & 7;
            *(float4*)&Ah[r * GM_STRIDE + c4 * 4] = *(const float4*)&Xh[(size_t)(m0 + r) * K2 + kc + c4 * 4];
            *(float4*)&Al[r * GM_STRIDE + c4 * 4] = *(const float4*)&Xl[(size_t)(m0 + r) * K2 + kc + c4 * 4];
            *(float4*)&Bh[r * GM_STRIDE + c4 * 4] = *(const float4*)&Wh[(size_t)(n0 + r) * K2 + kc + c4 * 4];
            *(float4*)&Bl[r * GM_STRIDE + c4 * 4] = *(const float4*)&Wl[(size_t)(n0 + r) * K2 + kc + c4 * 4];
        }
        __syncthreads();

        #pragma unroll
        for (int ks = 0; ks < 4; ks++) {
            uint32_t kb = (ks * 8) * 4;                // byte offset of k-step
            // B fragments: two x4 loads cover 4 n8 tiles (hi), two more (lo)
            unsigned bhf[2][4], blf[2][4];
            #pragma unroll
            for (int p = 0; p < 2; p++) {
                uint32_t ba = (brow_base + p * 16) * GM_STRIDE * 4 + kb + boff;
                LDSM_X4(bhf[p][0], bhf[p][1], bhf[p][2], bhf[p][3], sBh + ba);
                LDSM_X4(blf[p][0], blf[p][1], blf[p][2], blf[p][3], sBl + ba);
            }
            #pragma unroll
            for (int mt = 0; mt < 4; mt++) {
                uint32_t aa = (arow + mt * 16) * GM_STRIDE * 4 + kb + aoff;
                unsigned ah[4], al[4];
                LDSM_X4(ah[0], ah[1], ah[2], ah[3], sAh + aa);
                LDSM_X4(al[0], al[1], al[2], al[3], sAl + aa);
                #pragma unroll
                for (int nt = 0; nt < 4; nt++) {
                    unsigned b0 = bhf[nt >> 1][nt & 1], b1 = bhf[nt >> 1][2 + (nt & 1)];
                    unsigned c0 = blf[nt >> 1][nt & 1], c1 = blf[nt >> 1][2 + (nt & 1)];
                    mma_bf16(acc[mt][nt], ah[0], ah[1], ah[2], ah[3], b0, b1);
                    mma_bf16(acc[mt][nt], ah[0], ah[1], ah[2], ah[3], c0, c1);
                    mma_bf16(acc[mt][nt], al[0], al[1], al[2], al[3], b0, b1);
                }
            }
        }
    }

    int g = lane >> 2, t4 = lane & 3;
    #pragma unroll
    for (int mt = 0; mt < 4; mt++) {
        int row = m0 + wm * 64 + mt * 16 + g;
        #pragma unroll
        for (int nt = 0; nt < 4; nt++) {
            int col = n0 + wn * 32 + nt * 8 + 2 * t4;
            *(float2*)&C[(size_t)row * N + col]       = make_float2(acc[mt][nt][0], acc[mt][nt][1]);
            *(float2*)&C[(size_t)(row + 8) * N + col] = make_float2(acc[mt][nt][2], acc[mt][nt][3]);
        }
    }
}

// ======================= PBC expand + RoPE + pre-split ======================
__global__ __launch_bounds__(256)
void rope_expand_t(const int* __restrict__ outcell)
{
    __shared__ float sk[32][68];
    __shared__ float sv[32][68];
    int s0 = blockIdx.x * 32, h = blockIdx.y, b = blockIdx.z;
    int t = threadIdx.x;
    size_t bh = (size_t)b * NHh + h;
    const float LOG1E4 = 9.210340371976184f;

    #pragma unroll
    for (int i = 0; i < 2; i++) {
        int idx = t + i * 256;
        int r = idx >> 4, c4 = idx & 15;
        int s = s0 + r;
        int src = (s < Tt) ? s : outcell[b * Ee + (s - Tt)];
        *(float4*)&sk[r][c4 * 4] =
            ((const float4*)(g_kp + ((size_t)b * Tt + src) * Hh + h * 64))[c4];
        *(float4*)&sv[r][c4 * 4] =
            ((const float4*)(g_vp + ((size_t)b * Tt + src) * Hh + h * 64))[c4];
    }
    __syncthreads();

    // K: pairs along d, [bh][d2][s]
    #pragma unroll
    for (int i = 0; i < 4; i++) {
        int idx = t + i * 256;
        int d2 = idx >> 5, sl = idx & 31;
        int sabs = s0 + sl;
        int d0 = 2 * d2, d1 = d0 + 1;
        float invf0 = expf(-((float)(2 * (d0 & 31)) / 64.0f) * LOG1E4);
        float invf1 = expf(-((float)(2 * (d1 & 31)) / 64.0f) * LOG1E4);
        float a0 = (float)sabs * invf0, a1 = (float)sabs * invf1;
        float c0 = cosf(a0), n0 = sinf(a0), c1 = cosf(a1), n1 = sinf(a1);
        float v0 = (d0 < 32) ? sk[sl][d0] * c0 - sk[sl][d0 + 32] * n0
                             : sk[sl][d0] * c0 + sk[sl][d0 - 32] * n0;
        float v1 = (d1 < 32) ? sk[sl][d1] * c1 - sk[sl][d1 + 32] * n1
                             : sk[sl][d1] * c1 + sk[sl][d1 - 32] * n1;
        unsigned hp, lp; split2(v0, v1, hp, lp);
        g_kh[(bh * 32 + d2) * (size_t)Ss + sabs] = hp;
        g_kl[(bh * 32 + d2) * (size_t)Ss + sabs] = lp;
    }

    // V: pairs along s, [bh][s2][d]
    #pragma unroll
    for (int i = 0; i < 4; i++) {
        int idx = t + i * 256;
        int s2 = idx >> 6, d = idx & 63;
        unsigned hp, lp; split2(sv[2 * s2][d], sv[2 * s2 + 1][d], hp, lp);
        g_vh[(bh * 768 + (s0 >> 1) + s2) * 64 + d] = hp;
        g_vl[(bh * 768 + (s0 >> 1) + s2) * 64 + d] = lp;
    }

    if (s0 >= Tt) return;

    __syncthreads();
    #pragma unroll
    for (int i = 0; i < 2; i++) {
        int idx = t + i * 256;
        int r = idx >> 4, c4 = idx & 15;
        *(float4*)&sk[r][c4 * 4] =
            ((const float4*)(g_qp + ((size_t)b * Tt + s0 + r) * Hh + h * 64))[c4];
    }
    __syncthreads();
    // Q: pairs along d, [bh][q][d2]
    #pragma unroll
    for (int i = 0; i < 4; i++) {
        int idx = t + i * 256;
        int q = idx >> 5, d2 = idx & 31;
        int sabs = s0 + q;
        int d0 = 2 * d2, d1 = d0 + 1;
        float invf0 = expf(-((float)(2 * (d0 & 31)) / 64.0f) * LOG1E4);
        float invf1 = expf(-((float)(2 * (d1 & 31)) / 64.0f) * LOG1E4);
        float a0 = (float)sabs * invf0, a1 = (float)sabs * invf1;
        float c0 = cosf(a0), n0 = sinf(a0), c1 = cosf(a1), n1 = sinf(a1);
        float v0 = (d0 < 32) ? sk[q][d0] * c0 - sk[q][d0 + 32] * n0
                             : sk[q][d0] * c0 + sk[q][d0 - 32] * n0;
        float v1 = (d1 < 32) ? sk[q][d1] * c1 - sk[q][d1 + 32] * n1
                             : sk[q][d1] * c1 + sk[q][d1 - 32] * n1;
        unsigned hp, lp; split2(v0, v1, hp, lp);
        g_qh[((bh * Tt) + sabs) * 32 + d2] = hp;
        g_ql[((bh * Tt) + sabs) * 32 + d2] = lp;
    }
}

// ======================= Tensor-core flash attention ========================
#define ATT_SMEM_U32 (2*128*36 + 4*32*72 + 2*8*16*36)

__global__ __launch_bounds__(256)
void attn4(const float* __restrict__ bias, const float* __restrict__ lw,
           const unsigned char* __restrict__ kpm, const unsigned char* __restrict__ em)
{
    extern __shared__ unsigned su[];
    unsigned* Qh = su;                  // [128][36]
    unsigned* Ql = Qh + 128 * 36;
    unsigned* Kh = Ql + 128 * 36;       // [32][72]
    unsigned* Kl = Kh + 32 * 72;
    unsigned* Vh = Kl + 32 * 72;        // [32][72]
    unsigned* Vl = Vh + 32 * 72;
    unsigned* Ph = Vl + 32 * 72;        // per-warp [16][36]
    unsigned* Pl = Ph + 8 * 16 * 36;

    int t = threadIdx.x;
    int lane = t & 31, w = t >> 5;
    int g = lane >> 2, t4 = lane & 3;
    int qt = blockIdx.x, h = blockIdx.y, b = blockIdx.z;
    size_t bh = (size_t)b * NHh + h;
    int q0 = qt * 128;

    // stage Q (pre-split, packed pairs along d)
    #pragma unroll
    for (int i = 0; i < 4; i++) {
        int idx = t + i * 256;
        int q = idx >> 3, d4 = idx & 7;
        *(float4*)&Qh[q * 36 + d4 * 4] = *(const float4*)&g_qh[((bh * Tt) + q0 + q) * 32 + d4 * 4];
        *(float4*)&Ql[q * 36 + d4 * 4] = *(const float4*)&g_ql[((bh * Tt) + q0 + q) * 32 + d4 * 4];
    }

    float m0 = -INFINITY, m1 = -INFINITY, l0 = 0.f, l1 = 0.f;
    float oacc[8][4] = {};

    const float* biasr = bias + ((bh * Tt) + q0 + w * 16 + g) * (size_t)Ss;
    const float* lwr   = lw + ((size_t)b * Tt + q0 + w * 16 + g) * (size_t)Ss;
    unsigned* Phw = Ph + w * 16 * 36;
    unsigned* Plw = Pl + w * 16 * 36;

    for (int kt = 0; kt < Ss / 64; kt++) {
        int k0 = kt * 64;
        __syncthreads();
        #pragma unroll
        for (int i = 0; i < 2; i++) {
            int idx = t + i * 256;
            int r = idx >> 4, c4 = idx & 15;
            *(float4*)&Kh[r * 72 + c4 * 4] = *(const float4*)&g_kh[(bh * 32 + r) * (size_t)Ss + k0 + c4 * 4];
            *(float4*)&Kl[r * 72 + c4 * 4] = *(const float4*)&g_kl[(bh * 32 + r) * (size_t)Ss + k0 + c4 * 4];
            *(float4*)&Vh[r * 72 + c4 * 4] = *(const float4*)&g_vh[(bh * 768 + (k0 >> 1) + r) * 64 + c4 * 4];
            *(float4*)&Vl[r * 72 + c4 * 4] = *(const float4*)&g_vl[(bh * 768 + (k0 >> 1) + r) * 64 + c4 * 4];
        }
        __syncthreads();

        // QK: 16q x 64k per warp
        float sc[8][4];
        #pragma unroll
        for (int ns = 0; ns < 8; ns++)
            #pragma unroll
            for (int j = 0; j < 4; j++) sc[ns][j] = 0.f;

        int qb = w * 16;
        #pragma unroll
        for (int dc = 0; dc < 4; dc++) {
            unsigned ah0 = Qh[(qb + g) * 36 + dc * 8 + t4];
            unsigned ah1 = Qh[(qb + g + 8) * 36 + dc * 8 + t4];
            unsigned ah2 = Qh[(qb + g) * 36 + dc * 8 + t4 + 4];
            unsigned ah3 = Qh[(qb + g + 8) * 36 + dc * 8 + t4 + 4];
            unsigned al0 = Ql[(qb + g) * 36 + dc * 8 + t4];
            unsigned al1 = Ql[(qb + g + 8) * 36 + dc * 8 + t4];
            unsigned al2 = Ql[(qb + g) * 36 + dc * 8 + t4 + 4];
            unsigned al3 = Ql[(qb + g + 8) * 36 + dc * 8 + t4 + 4];
            #pragma unroll
            for (int ns = 0; ns < 8; ns++) {
                unsigned bh0 = Kh[(dc * 8 + t4) * 72 + ns * 8 + g];
                unsigned bh1 = Kh[(dc * 8 + t4 + 4) * 72 + ns * 8 + g];
                unsigned bl0 = Kl[(dc * 8 + t4) * 72 + ns * 8 + g];
                unsigned bl1 = Kl[(dc * 8 + t4 + 4) * 72 + ns * 8 + g];
                mma_bf16(sc[ns], ah0, ah1, ah2, ah3, bh0, bh1);
                mma_bf16(sc[ns], ah0, ah1, ah2, ah3, bl0, bl1);
                mma_bf16(sc[ns], al0, al1, al2, al3, bh0, bh1);
            }
        }

        // bias + masks
        float lwv[8][4];
        float tm0 = -INFINITY, tm1 = -INFINITY;
        #pragma unroll
        for (int ns = 0; ns < 8; ns++) {
            int kb = k0 + ns * 8 + 2 * t4;
            float2 b0v = *(const float2*)(biasr + kb);
            float2 b1v = *(const float2*)(biasr + 8 * (size_t)Ss + kb);
            float2 l0v = *(const float2*)(lwr + kb);
            float2 l1v = *(const float2*)(lwr + 8 * (size_t)Ss + kb);
            unsigned char ma0, ma1;
            if (k0 < Tt) { ma0 = kpm[b * Tt + kb]; ma1 = kpm[b * Tt + kb + 1]; }
            else         { ma0 = em[b * Ee + kb - Tt]; ma1 = em[b * Ee + kb - Tt + 1]; }
            sc[ns][0] = (l0v.x <= 1e-5f || ma0) ? -INFINITY : sc[ns][0] + b0v.x;
            sc[ns][1] = (l0v.y <= 1e-5f || ma1) ? -INFINITY : sc[ns][1] + b0v.y;
            sc[ns][2] = (l1v.x <= 1e-5f || ma0) ? -INFINITY : sc[ns][2] + b1v.x;
            sc[ns][3] = (l1v.y <= 1e-5f || ma1) ? -INFINITY : sc[ns][3] + b1v.y;
            lwv[ns][0] = l0v.x; lwv[ns][1] = l0v.y;
            lwv[ns][2] = l1v.x; lwv[ns][3] = l1v.y;
            tm0 = fmaxf(tm0, fmaxf(sc[ns][0], sc[ns][1]));
            tm1 = fmaxf(tm1, fmaxf(sc[ns][2], sc[ns][3]));
        }
        tm0 = fmaxf(tm0, __shfl_xor_sync(0xffffffffu, tm0, 1));
        tm0 = fmaxf(tm0, __shfl_xor_sync(0xffffffffu, tm0, 2));
        tm1 = fmaxf(tm1, __shfl_xor_sync(0xffffffffu, tm1, 1));
        tm1 = fmaxf(tm1, __shfl_xor_sync(0xffffffffu, tm1, 2));

        float mn0 = fmaxf(m0, tm0);
        float mn1 = fmaxf(m1, tm1);
        float scl0 = (mn0 > -INFINITY) ? __expf(m0 - mn0) : 1.0f;
        float scl1 = (mn1 > -INFINITY) ? __expf(m1 - mn1) : 1.0f;
        float mc0 = (mn0 > -INFINITY) ? mn0 : 0.0f;
        float mc1 = (mn1 > -INFINITY) ? mn1 : 0.0f;

        float es0 = 0.f, es1 = 0.f;
        #pragma unroll
        for (int ns = 0; ns < 8; ns++) {
            float e0 = __expf(sc[ns][0] - mc0);
            float e1 = __expf(sc[ns][1] - mc0);
            float e2 = __expf(sc[ns][2] - mc1);
            float e3 = __expf(sc[ns][3] - mc1);
            es0 += e0 + e1; es1 += e2 + e3;
            unsigned hp, lp;
            split2(e0 * lwv[ns][0], e1 * lwv[ns][1], hp, lp);
            Phw[g * 36 + ns * 4 + t4] = hp;
            Plw[g * 36 + ns * 4 + t4] = lp;
            split2(e2 * lwv[ns][2], e3 * lwv[ns][3], hp, lp);
            Phw[(g + 8) * 36 + ns * 4 + t4] = hp;
            Plw[(g + 8) * 36 + ns * 4 + t4] = lp;
        }
        es0 += __shfl_xor_sync(0xffffffffu, es0, 1);
        es0 += __shfl_xor_sync(0xffffffffu, es0, 2);
        es1 += __shfl_xor_sync(0xffffffffu, es1, 1);
        es1 += __shfl_xor_sync(0xffffffffu, es1, 2);
        l0 = l0 * scl0 + es0; m0 = mn0;
        l1 = l1 * scl1 + es1; m1 = mn1;

        #pragma unroll
        for (int ns = 0; ns < 8; ns++) {
            oacc[ns][0] *= scl0; oacc[ns][1] *= scl0;
            oacc[ns][2] *= scl1; oacc[ns][3] *= scl1;
        }
        __syncwarp();

        // PV
        #pragma unroll
        for (int kc = 0; kc < 4; kc++) {
            unsigned ah0 = Phw[g * 36 + kc * 8 + t4];
            unsigned ah1 = Phw[(g + 8) * 36 + kc * 8 + t4];
            unsigned ah2 = Phw[g * 36 + kc * 8 + t4 + 4];
            unsigned ah3 = Phw[(g + 8) * 36 + kc * 8 + t4 + 4];
            unsigned al0 = Plw[g * 36 + kc * 8 + t4];
            unsigned al1 = Plw[(g + 8) * 36 + kc * 8 + t4];
            unsigned al2 = Plw[g * 36 + kc * 8 + t4 + 4];
            unsigned al3 = Plw[(g + 8) * 36 + kc * 8 + t4 + 4];
            #pragma unroll
            for (int ns = 0; ns < 8; ns++) {
                unsigned b0 = Vh[(kc * 8 + t4) * 72 + ns * 8 + g];
                unsigned b1 = Vh[(kc * 8 + t4 + 4) * 72 + ns * 8 + g];
                unsigned c0 = Vl[(kc * 8 + t4) * 72 + ns * 8 + g];
                unsigned c1 = Vl[(kc * 8 + t4 + 4) * 72 + ns * 8 + g];
                mma_bf16(oacc[ns], ah0, ah1, ah2, ah3, b0, b1);
                mma_bf16(oacc[ns], ah0, ah1, ah2, ah3, c0, c1);
                mma_bf16(oacc[ns], al0, al1, al2, al3, b0, b1);
            }
        }
    }

    float i0 = 1.0f / l0, i1 = 1.0f / l1;
    int r0 = q0 + w * 16 + g;
    #pragma unroll
    for (int ns = 0; ns < 8; ns++) {
        float2 o0 = make_float2(oacc[ns][0] * i0, oacc[ns][1] * i0);
        float2 o1 = make_float2(oacc[ns][2] * i1, oacc[ns][3] * i1);
        *(float2*)&g_attn[((size_t)b * Tt + r0) * Hh + h * 64 + ns * 8 + 2 * t4] = o0;
        *(float2*)&g_attn[((size_t)b * Tt + r0 + 8) * Hh + h * 64 + ns * 8 + 2 * t4] = o1;
    }
}

// ---- layernorm over H=1024, emits packed hi/lo for out-proj GEMM ----
__global__ void ln_kernel(const float* __restrict__ gamma, const float* __restrict__ beta)
{
    int row = blockIdx.x;
    int tid = threadIdx.x;
    float4 v = *(const float4*)&g_attn[(size_t)row * Hh + tid * 4];
    float s = v.x + v.y + v.z + v.w;
    float s2 = v.x * v.x + v.y * v.y + v.z * v.z + v.w * v.w;
    __shared__ float rs[256], rs2[256];
    rs[tid] = s; rs2[tid] = s2;
    __syncthreads();
    for (int st = 128; st > 0; st >>= 1) {
        if (tid < st) { rs[tid] += rs[tid + st]; rs2[tid] += rs2[tid + st]; }
        __syncthreads();
    }
    float mean = rs[0] * (1.0f / Hh);
    float var  = rs2[0] * (1.0f / Hh) - mean * mean;
    float r = rsqrtf(var + 1e-5f);
    float4 gm = *(const float4*)&gamma[tid * 4];
    float4 bt = *(const float4*)&beta[tid * 4];
    float n0 = (v.x - mean) * r * gm.x + bt.x;
    float n1 = (v.y - mean) * r * gm.y + bt.y;
    float n2 = (v.z - mean) * r * gm.z + bt.z;
    float n3 = (v.w - mean) * r * gm.w + bt.w;
    unsigned h0, l0v, h1, l1v;
    split2(n0, n1, h0, l0v);
    split2(n2, n3, h1, l1v);
    *(uint2*)&g_nh[(size_t)row * 512 + tid * 2] = make_uint2(h0, h1);
    *(uint2*)&g_nl[(size_t)row * 512 + tid * 2] = make_uint2(l0v, l1v);
}

extern "C" void kernel_launch(void* const* d_in, const int* in_sizes, int n_in,
                              void* d_out, int out_size)
{
    const float* x    = (const float*)d_in[0];
    const float* bias = (const float*)d_in[1];
    const float* lw   = (const float*)d_in[2];
    const unsigned char* kpm = (const unsigned char*)d_in[3];
    const int*   outcell = (const int*)d_in[4];
    const unsigned char* em  = (const unsigned char*)d_in[5];
    const float* wq   = (const float*)d_in[6];
    const float* wk   = (const float*)d_in[7];
    const float* wv   = (const float*)d_in[8];
    const float* wout = (const float*)d_in[9];
    const float* lng  = (const float*)d_in[10];
    const float* lnb  = (const float*)d_in[11];

    float *qp, *kp, *vp;
    unsigned *xh, *xl, *wqh, *wql, *wkh, *wkl, *wvh, *wvl, *woh, *wol, *nh, *nl;
    cudaGetSymbolAddress((void**)&qp,  g_qp);
    cudaGetSymbolAddress((void**)&kp,  g_kp);
    cudaGetSymbolAddress((void**)&vp,  g_vp);
    cudaGetSymbolAddress((void**)&xh,  g_xh);  cudaGetSymbolAddress((void**)&xl,  g_xl);
    cudaGetSymbolAddress((void**)&wqh, g_wqh); cudaGetSymbolAddress((void**)&wql, g_wql);
    cudaGetSymbolAddress((void**)&wkh, g_wkh); cudaGetSymbolAddress((void**)&wkl, g_wkl);
    cudaGetSymbolAddress((void**)&wvh, g_wvh); cudaGetSymbolAddress((void**)&wvl, g_wvl);
    cudaGetSymbolAddress((void**)&woh, g_woh); cudaGetSymbolAddress((void**)&wol, g_wol);
    cudaGetSymbolAddress((void**)&nh,  g_nh);  cudaGetSymbolAddress((void**)&nl,  g_nl);

    static int attr_set = 0;
    if (!attr_set) {
        cudaFuncSetAttribute(attn4, cudaFuncAttributeMaxDynamicSharedMemorySize,
                             ATT_SMEM_U32 * 4);
        cudaFuncSetAttribute(gemm_mma, cudaFuncAttributeMaxDynamicSharedMemorySize,
                             GM_SMEM_BYTES);
        attr_set = 1;
    }

    // pre-split inputs/weights to packed bf16 hi/lo (wq scaled by 0.125)
    int xp = Bb * Tt * Hh / 2, wp = Hh * Hh / 2;
    splitk<<<(xp + 255) / 256, 256>>>(x, xh, xl, xp, 1.0f);
    splitk<<<(wp + 255) / 256, 256>>>(wq, wqh, wql, wp, 0.125f);
    splitk<<<(wp + 255) / 256, 256>>>(wk, wkh, wkl, wp, 1.0f);
    splitk<<<(wp + 255) / 256, 256>>>(wv, wvh, wvl, wp, 1.0f);
    splitk<<<(wp + 255) / 256, 256>>>(wout, woh, wol, wp, 1.0f);

    // QKV projection on tensor cores
    gemm_mma<<<dim3(Hh / 128, (Bb * Tt) / 128, 3), 256, GM_SMEM_BYTES>>>(
        xh, xl, wqh, wql, wkh, wkl, wvh, wvl, qp, kp, vp, Hh, Hh);

    rope_expand_t<<<dim3(Ss / 32, NHh, Bb), 256>>>(outcell);

    attn4<<<dim3(Tt / 128, NHh, Bb), 256, ATT_SMEM_U32 * 4>>>(bias, lw, kpm, em);

    ln_kernel<<<Bb * Tt, 256>>>(lng, lnb);

    // output projection on tensor cores
    gemm_mma<<<dim3(Hh / 128, (Bb * Tt) / 128, 1), 256, GM_SMEM_BYTES>>>(
        nh, nl, woh, wol, woh, wol, woh, wol,
        (float*)d_out, (float*)d_out, (float*)d_out, Hh, Hh);
}